// round 2
// baseline (speedup 1.0000x reference)
#include <cuda_runtime.h>
#include <math.h>

#define NN 8192
#define NE 262144
#define DD 128
#define HH 256
#define DHH 64
#define EDD 16
#define YY 64

__device__ float g_agg[NN * HH];
__device__ float g_xgnn[NN * DD];
__device__ float g_q[NN * DHH];
__device__ float g_k[NN * DHH];
__device__ float g_v[NN * DHH];
__device__ float g_oh[NN * DHH];

__device__ __forceinline__ float silu_f(float v) { return v / (1.0f + __expf(-v)); }

__global__ void zero_agg_kernel() {
    int i = blockIdx.x * blockDim.x + threadIdx.x;
    ((float4*)g_agg)[i] = make_float4(0.f, 0.f, 0.f, 0.f);
}

// ================= edge MLP + segment_sum =================
#define EDGE_SMEM ((64 * 292 + 16 * 260) * 4 + 64 * 2 * 4)
__global__ __launch_bounds__(256, 2) void edge_kernel(
    const float* __restrict__ x, const float* __restrict__ coords,
    const float* __restrict__ eattr, const int* __restrict__ eidx,
    const float* __restrict__ ew1, const float* __restrict__ eb1,
    const float* __restrict__ ew2, const float* __restrict__ eb2)
{
    extern __shared__ float sm[];
    float* sM = sm;                       // [64][292] input, reused as sH[64][260]
    float* sW = sm + 64 * 292;            // [16][260]
    int* sRow = (int*)(sW + 16 * 260);
    int* sCol = sRow + 64;

    const int t = threadIdx.x, e0 = blockIdx.x * 64;
    const int ty = t >> 4, tx = t & 15, r0 = ty << 2, c0 = tx << 4;

    if (t < 64) {
        int e = e0 + t;
        int r = eidx[e], c = eidx[NE + e];
        sRow[t] = r; sCol[t] = c;
        float dx = coords[3*r+0]-coords[3*c+0];
        float dy = coords[3*r+1]-coords[3*c+1];
        float dz = coords[3*r+2]-coords[3*c+2];
        sM[t*292 + 256] = dx*dx + dy*dy + dz*dz;
        for (int j = 0; j < 15; j++) sM[t*292 + 273 + j] = 0.f;
    }
    __syncthreads();

    const float4* x4 = (const float4*)x;
    float4* sM4 = (float4*)sM;            // row stride 73 float4
    for (int idx = t; idx < 64*32; idx += 256) {
        int e = idx >> 5, f = idx & 31;
        sM4[e*73 + f] = x4[sRow[e]*32 + f];
    }
    for (int idx = t; idx < 64*32; idx += 256) {
        int e = idx >> 5, f = idx & 31;
        sM4[e*73 + 32 + f] = x4[sCol[e]*32 + f];
    }
    for (int idx = t; idx < 64*EDD; idx += 256) {
        int e = idx >> 4, j = idx & 15;
        sM[e*292 + 257 + j] = eattr[(e0+e)*EDD + j];
    }
    __syncthreads();

    float acc[4][16];
#pragma unroll
    for (int i = 0; i < 4; i++)
#pragma unroll
        for (int j = 0; j < 16; j++) acc[i][j] = 0.f;

    for (int k0 = 0; k0 < 288; k0 += 16) {
        int kg = k0 + ty;
        float4* sWr = (float4*)(sW + ty*260);
        if (kg < 273) {
            const float4* w4 = (const float4*)(ew1 + kg*HH);
#pragma unroll
            for (int j = 0; j < 4; j++) sWr[tx*4+j] = w4[tx*4+j];
        } else {
#pragma unroll
            for (int j = 0; j < 4; j++) sWr[tx*4+j] = make_float4(0.f,0.f,0.f,0.f);
        }
        __syncthreads();
#pragma unroll
        for (int kk = 0; kk < 16; kk++) {
            float w[16];
            const float4* wp = (const float4*)(sW + kk*260 + c0);
            *((float4*)&w[0]) = wp[0]; *((float4*)&w[4]) = wp[1];
            *((float4*)&w[8]) = wp[2]; *((float4*)&w[12]) = wp[3];
            float a0 = sM[(r0+0)*292 + k0+kk], a1 = sM[(r0+1)*292 + k0+kk];
            float a2 = sM[(r0+2)*292 + k0+kk], a3 = sM[(r0+3)*292 + k0+kk];
#pragma unroll
            for (int j = 0; j < 16; j++) {
                acc[0][j] = fmaf(a0, w[j], acc[0][j]);
                acc[1][j] = fmaf(a1, w[j], acc[1][j]);
                acc[2][j] = fmaf(a2, w[j], acc[2][j]);
                acc[3][j] = fmaf(a3, w[j], acc[3][j]);
            }
        }
        __syncthreads();
    }

    float* sH = sm;  // [64][260]
#pragma unroll
    for (int i = 0; i < 4; i++)
#pragma unroll
        for (int j = 0; j < 16; j++)
            sH[(r0+i)*260 + c0+j] = silu_f(acc[i][j] + eb1[c0+j]);
    __syncthreads();

    float acc2[4][16];
#pragma unroll
    for (int i = 0; i < 4; i++)
#pragma unroll
        for (int j = 0; j < 16; j++) acc2[i][j] = 0.f;

    for (int k0 = 0; k0 < 256; k0 += 16) {
        float4* sWr = (float4*)(sW + ty*260);
        const float4* w4 = (const float4*)(ew2 + (k0+ty)*HH);
#pragma unroll
        for (int j = 0; j < 4; j++) sWr[tx*4+j] = w4[tx*4+j];
        __syncthreads();
#pragma unroll
        for (int kk = 0; kk < 16; kk++) {
            float w[16];
            const float4* wp = (const float4*)(sW + kk*260 + c0);
            *((float4*)&w[0]) = wp[0]; *((float4*)&w[4]) = wp[1];
            *((float4*)&w[8]) = wp[2]; *((float4*)&w[12]) = wp[3];
            float a0 = sH[(r0+0)*260 + k0+kk], a1 = sH[(r0+1)*260 + k0+kk];
            float a2 = sH[(r0+2)*260 + k0+kk], a3 = sH[(r0+3)*260 + k0+kk];
#pragma unroll
            for (int j = 0; j < 16; j++) {
                acc2[0][j] = fmaf(a0, w[j], acc2[0][j]);
                acc2[1][j] = fmaf(a1, w[j], acc2[1][j]);
                acc2[2][j] = fmaf(a2, w[j], acc2[2][j]);
                acc2[3][j] = fmaf(a3, w[j], acc2[3][j]);
            }
        }
        __syncthreads();
    }

#pragma unroll
    for (int i = 0; i < 4; i++) {
        int node = sRow[r0+i];
#pragma unroll
        for (int j = 0; j < 16; j++)
            atomicAdd(&g_agg[node*HH + c0+j], silu_f(acc2[i][j] + eb2[c0+j]));
    }
}

// ================= node MLP + residual =================
#define NODE_SMEM ((64 * 388 + 16 * 260) * 4)
__global__ __launch_bounds__(256, 1) void node_kernel(
    const float* __restrict__ x,
    const float* __restrict__ nw1, const float* __restrict__ nb1,
    const float* __restrict__ nw2, const float* __restrict__ nb2)
{
    extern __shared__ float sm[];
    float* sM = sm;                 // [64][388], reused as sH[64][260]
    float* sW = sm + 64 * 388;      // [16][260] / [16][132]

    const int t = threadIdx.x, n0 = blockIdx.x * 64;
    const int ty = t >> 4, tx = t & 15, r0 = ty << 2;

    const float4* x4 = (const float4*)x;
    const float4* agg4 = (const float4*)g_agg;
    float4* sM4 = (float4*)sM;      // stride 97
    for (int idx = t; idx < 64*32; idx += 256) {
        int e = idx >> 5, f = idx & 31;
        sM4[e*97 + f] = x4[(n0+e)*32 + f];
    }
    for (int idx = t; idx < 64*64; idx += 256) {
        int e = idx >> 6, f = idx & 63;
        sM4[e*97 + 32 + f] = agg4[(n0+e)*64 + f];
    }
    __syncthreads();

    const int c0 = tx << 4;
    float acc[4][16];
#pragma unroll
    for (int i = 0; i < 4; i++)
#pragma unroll
        for (int j = 0; j < 16; j++) acc[i][j] = 0.f;

    for (int k0 = 0; k0 < 384; k0 += 16) {
        float4* sWr = (float4*)(sW + ty*260);
        const float4* w4 = (const float4*)(nw1 + (k0+ty)*HH);
#pragma unroll
        for (int j = 0; j < 4; j++) sWr[tx*4+j] = w4[tx*4+j];
        __syncthreads();
#pragma unroll
        for (int kk = 0; kk < 16; kk++) {
            float w[16];
            const float4* wp = (const float4*)(sW + kk*260 + c0);
            *((float4*)&w[0]) = wp[0]; *((float4*)&w[4]) = wp[1];
            *((float4*)&w[8]) = wp[2]; *((float4*)&w[12]) = wp[3];
            float a0 = sM[(r0+0)*388 + k0+kk], a1 = sM[(r0+1)*388 + k0+kk];
            float a2 = sM[(r0+2)*388 + k0+kk], a3 = sM[(r0+3)*388 + k0+kk];
#pragma unroll
            for (int j = 0; j < 16; j++) {
                acc[0][j] = fmaf(a0, w[j], acc[0][j]);
                acc[1][j] = fmaf(a1, w[j], acc[1][j]);
                acc[2][j] = fmaf(a2, w[j], acc[2][j]);
                acc[3][j] = fmaf(a3, w[j], acc[3][j]);
            }
        }
        __syncthreads();
    }

    float* sH = sm;
#pragma unroll
    for (int i = 0; i < 4; i++)
#pragma unroll
        for (int j = 0; j < 16; j++)
            sH[(r0+i)*260 + c0+j] = silu_f(acc[i][j] + nb1[c0+j]);
    __syncthreads();

    const int c1 = tx << 3;
    float acc2[4][8];
#pragma unroll
    for (int i = 0; i < 4; i++)
#pragma unroll
        for (int j = 0; j < 8; j++) acc2[i][j] = 0.f;

    for (int k0 = 0; k0 < 256; k0 += 16) {
        float4* sWr = (float4*)(sW + ty*132);
        const float4* w4 = (const float4*)(nw2 + (k0+ty)*DD);
        sWr[tx*2+0] = w4[tx*2+0];
        sWr[tx*2+1] = w4[tx*2+1];
        __syncthreads();
#pragma unroll
        for (int kk = 0; kk < 16; kk++) {
            float w[8];
            const float4* wp = (const float4*)(sW + kk*132 + c1);
            *((float4*)&w[0]) = wp[0]; *((float4*)&w[4]) = wp[1];
            float a0 = sH[(r0+0)*260 + k0+kk], a1 = sH[(r0+1)*260 + k0+kk];
            float a2 = sH[(r0+2)*260 + k0+kk], a3 = sH[(r0+3)*260 + k0+kk];
#pragma unroll
            for (int j = 0; j < 8; j++) {
                acc2[0][j] = fmaf(a0, w[j], acc2[0][j]);
                acc2[1][j] = fmaf(a1, w[j], acc2[1][j]);
                acc2[2][j] = fmaf(a2, w[j], acc2[2][j]);
                acc2[3][j] = fmaf(a3, w[j], acc2[3][j]);
            }
        }
        __syncthreads();
    }

#pragma unroll
    for (int i = 0; i < 4; i++) {
        int node = n0 + r0 + i;
        float4 xa = x4[node*32 + (c1>>2)];
        float4 xb = x4[node*32 + (c1>>2) + 1];
        float4 o0, o1;
        o0.x = acc2[i][0]+nb2[c1+0]+xa.x; o0.y = acc2[i][1]+nb2[c1+1]+xa.y;
        o0.z = acc2[i][2]+nb2[c1+2]+xa.z; o0.w = acc2[i][3]+nb2[c1+3]+xa.w;
        o1.x = acc2[i][4]+nb2[c1+4]+xb.x; o1.y = acc2[i][5]+nb2[c1+5]+xb.y;
        o1.z = acc2[i][6]+nb2[c1+6]+xb.z; o1.w = acc2[i][7]+nb2[c1+7]+xb.w;
        ((float4*)g_xgnn)[node*32 + (c1>>2)]     = o0;
        ((float4*)g_xgnn)[node*32 + (c1>>2) + 1] = o1;
    }
}

// ================= QKV projection =================
#define QKV_SMEM ((64 * 132 + 128 * 68) * 4)
__global__ __launch_bounds__(256, 2) void qkv_kernel(
    const float* __restrict__ x, const float* __restrict__ wq,
    const float* __restrict__ wk, const float* __restrict__ wv)
{
    extern __shared__ float sm[];
    float* sX = sm;              // [64][132]
    float* sW = sm + 64 * 132;   // [128][68]

    const int t = threadIdx.x, n0 = blockIdx.x * 64;
    const float* w = (blockIdx.y == 0) ? wq : (blockIdx.y == 1) ? wk : wv;
    float* o = (blockIdx.y == 0) ? g_q : (blockIdx.y == 1) ? g_k : g_v;

    const float4* x4 = (const float4*)x;
    float4* sX4 = (float4*)sX;   // stride 33
    for (int idx = t; idx < 64*32; idx += 256) {
        int e = idx >> 5, f = idx & 31;
        sX4[e*33 + f] = x4[(n0+e)*32 + f];
    }
    const float4* w4 = (const float4*)w;
    float4* sW4 = (float4*)sW;   // stride 17
    for (int idx = t; idx < 128*16; idx += 256) {
        int r = idx >> 4, f = idx & 15;
        sW4[r*17 + f] = w4[r*16 + f];
    }
    __syncthreads();

    const int ty = t >> 4, tx = t & 15, r0 = ty << 2;
    float acc[4][4];
#pragma unroll
    for (int i = 0; i < 4; i++)
#pragma unroll
        for (int j = 0; j < 4; j++) acc[i][j] = 0.f;

    for (int k = 0; k < 128; k++) {
        float4 wv4 = sW4[k*17 + tx];
#pragma unroll
        for (int i = 0; i < 4; i++) {
            float a = sX[(r0+i)*132 + k];
            acc[i][0] = fmaf(a, wv4.x, acc[i][0]);
            acc[i][1] = fmaf(a, wv4.y, acc[i][1]);
            acc[i][2] = fmaf(a, wv4.z, acc[i][2]);
            acc[i][3] = fmaf(a, wv4.w, acc[i][3]);
        }
    }
#pragma unroll
    for (int i = 0; i < 4; i++)
        ((float4*)o)[(n0+r0+i)*16 + tx] =
            make_float4(acc[i][0], acc[i][1], acc[i][2], acc[i][3]);
}

// ================= radius-masked flash attention =================
__global__ __launch_bounds__(256) void attn_kernel(const float* __restrict__ coords)
{
    __shared__ float sK[64][68];
    __shared__ float sV[64][68];
    __shared__ float sC[64][4];

    const int t = threadIdx.x;
    const int g = t & 3;          // dim group (16 dims)
    const int rl = t >> 2;
    const int row = blockIdx.x * 64 + rl;

    float q[16];
    {
        const float4* q4 = (const float4*)(g_q + row*DHH + g*16);
        float4 a = q4[0], b = q4[1], c = q4[2], d = q4[3];
        q[0]=a.x;q[1]=a.y;q[2]=a.z;q[3]=a.w; q[4]=b.x;q[5]=b.y;q[6]=b.z;q[7]=b.w;
        q[8]=c.x;q[9]=c.y;q[10]=c.z;q[11]=c.w; q[12]=d.x;q[13]=d.y;q[14]=d.z;q[15]=d.w;
    }
    const float cx = coords[row*3+0], cy = coords[row*3+1], cz = coords[row*3+2];

    float m = -INFINITY, l = 0.f;
    float o[16];
#pragma unroll
    for (int i = 0; i < 16; i++) o[i] = 0.f;

    for (int j0 = 0; j0 < NN; j0 += 64) {
        for (int idx = t; idx < 64*16; idx += 256) {
            int jj = idx >> 4, f = idx & 15;
            ((float4*)&sK[jj][0])[f] = ((const float4*)g_k)[(j0+jj)*16 + f];
            ((float4*)&sV[jj][0])[f] = ((const float4*)g_v)[(j0+jj)*16 + f];
        }
        {
            int jj = t >> 2, cc = t & 3;
            sC[jj][cc] = (cc < 3) ? coords[(j0+jj)*3 + cc] : 0.f;
        }
        __syncthreads();

        for (int j = 0; j < 64; j++) {
            float dx = cx - sC[j][0], dy = cy - sC[j][1], dz = cz - sC[j][2];
            float d2 = dx*dx + dy*dy + dz*dz;

            const float4* kp = (const float4*)&sK[j][g*16];
            float4 k0 = kp[0], k1 = kp[1], k2 = kp[2], k3 = kp[3];
            float p = q[0]*k0.x+q[1]*k0.y+q[2]*k0.z+q[3]*k0.w
                    + q[4]*k1.x+q[5]*k1.y+q[6]*k1.z+q[7]*k1.w
                    + q[8]*k2.x+q[9]*k2.y+q[10]*k2.z+q[11]*k2.w
                    + q[12]*k3.x+q[13]*k3.y+q[14]*k3.z+q[15]*k3.w;
            p += __shfl_xor_sync(0xffffffffu, p, 1);
            p += __shfl_xor_sync(0xffffffffu, p, 2);

            if (d2 <= 100.0f) {
                float s = p * 0.125f;
                if (s > m) {
                    float corr = __expf(m - s);
                    l *= corr;
#pragma unroll
                    for (int i = 0; i < 16; i++) o[i] *= corr;
                    m = s;
                }
                float w = __expf(s - m);
                l += w;
                const float4* vp = (const float4*)&sV[j][g*16];
                float4 v0 = vp[0], v1 = vp[1], v2 = vp[2], v3 = vp[3];
                o[0]=fmaf(w,v0.x,o[0]); o[1]=fmaf(w,v0.y,o[1]); o[2]=fmaf(w,v0.z,o[2]); o[3]=fmaf(w,v0.w,o[3]);
                o[4]=fmaf(w,v1.x,o[4]); o[5]=fmaf(w,v1.y,o[5]); o[6]=fmaf(w,v1.z,o[6]); o[7]=fmaf(w,v1.w,o[7]);
                o[8]=fmaf(w,v2.x,o[8]); o[9]=fmaf(w,v2.y,o[9]); o[10]=fmaf(w,v2.z,o[10]); o[11]=fmaf(w,v2.w,o[11]);
                o[12]=fmaf(w,v3.x,o[12]); o[13]=fmaf(w,v3.y,o[13]); o[14]=fmaf(w,v3.z,o[14]); o[15]=fmaf(w,v3.w,o[15]);
            }
        }
        __syncthreads();
    }

    float inv = 1.0f / l;
    float4* oh4 = (float4*)(g_oh + row*DHH + g*16);
    oh4[0] = make_float4(o[0]*inv, o[1]*inv, o[2]*inv, o[3]*inv);
    oh4[1] = make_float4(o[4]*inv, o[5]*inv, o[6]*inv, o[7]*inv);
    oh4[2] = make_float4(o[8]*inv, o[9]*inv, o[10]*inv, o[11]*inv);
    oh4[3] = make_float4(o[12]*inv, o[13]*inv, o[14]*inv, o[15]*inv);
}

// ================= combiner: wo-GEMM + residual + MLP + LayerNorm =================
// smem floats: sC[64][132] @0, sH[64][260] @8448, sW[16][260] @25088
// phase A aliases: sOH[64][68] @8448, sWo[64][132] @12800
#define CMB_SMEM (29248 * 4)
__global__ __launch_bounds__(256, 1) void comb_kernel(
    const float* __restrict__ wo,
    const float* __restrict__ cmw1, const float* __restrict__ cmb1,
    const float* __restrict__ ln_g, const float* __restrict__ ln_b,
    const float* __restrict__ cmw2, const float* __restrict__ cmb2,
    float* __restrict__ out)
{
    extern __shared__ float sm[];
    float* sC = sm;
    float* sH = sm + 8448;
    float* sW = sm + 25088;
    float* sOH = sm + 8448;
    float* sWo = sm + 12800;

    const int t = threadIdx.x, n0 = blockIdx.x * 64;
    const int ty = t >> 4, tx = t & 15, r0 = ty << 2;

    // ---- phase A: combined = x_gnn + oh @ wo ----
    for (int idx = t; idx < 64*16; idx += 256) {
        int e = idx >> 4, f = idx & 15;
        ((float4*)sOH)[e*17 + f] = ((const float4*)g_oh)[(n0+e)*16 + f];
    }
    for (int idx = t; idx < 64*32; idx += 256) {
        int r = idx >> 5, f = idx & 31;
        ((float4*)sWo)[r*33 + f] = ((const float4*)wo)[r*32 + f];
    }
    __syncthreads();

    {
        const int c1 = tx << 3;
        float acc[4][8];
#pragma unroll
        for (int i = 0; i < 4; i++)
#pragma unroll
            for (int j = 0; j < 8; j++) acc[i][j] = 0.f;
        for (int k = 0; k < 64; k++) {
            float4 w0 = ((float4*)sWo)[k*33 + (c1>>2)];
            float4 w1 = ((float4*)sWo)[k*33 + (c1>>2) + 1];
#pragma unroll
            for (int i = 0; i < 4; i++) {
                float a = sOH[(r0+i)*68 + k];
                acc[i][0]=fmaf(a,w0.x,acc[i][0]); acc[i][1]=fmaf(a,w0.y,acc[i][1]);
                acc[i][2]=fmaf(a,w0.z,acc[i][2]); acc[i][3]=fmaf(a,w0.w,acc[i][3]);
                acc[i][4]=fmaf(a,w1.x,acc[i][4]); acc[i][5]=fmaf(a,w1.y,acc[i][5]);
                acc[i][6]=fmaf(a,w1.z,acc[i][6]); acc[i][7]=fmaf(a,w1.w,acc[i][7]);
            }
        }
        __syncthreads();   // phase A reads done before sC (aliases nothing) writes? sC separate; but sOH/sWo die after
#pragma unroll
        for (int i = 0; i < 4; i++)
#pragma unroll
            for (int j = 0; j < 8; j++)
                sC[(r0+i)*132 + c1+j] = acc[i][j] + g_xgnn[(n0+r0+i)*128 + c1+j];
    }
    __syncthreads();

    // ---- phase B: h2 = relu(sC @ cmw1 + cmb1) ----
    {
        const int c0 = tx << 4;
        float acc[4][16];
#pragma unroll
        for (int i = 0; i < 4; i++)
#pragma unroll
            for (int j = 0; j < 16; j++) acc[i][j] = 0.f;
        for (int k0 = 0; k0 < 128; k0 += 16) {
            float4* sWr = (float4*)(sW + ty*260);
            const float4* w4 = (const float4*)(cmw1 + (k0+ty)*HH);
#pragma unroll
            for (int j = 0; j < 4; j++) sWr[tx*4+j] = w4[tx*4+j];
            __syncthreads();
#pragma unroll
            for (int kk = 0; kk < 16; kk++) {
                float w[16];
                const float4* wp = (const float4*)(sW + kk*260 + c0);
                *((float4*)&w[0]) = wp[0]; *((float4*)&w[4]) = wp[1];
                *((float4*)&w[8]) = wp[2]; *((float4*)&w[12]) = wp[3];
                float a0 = sC[(r0+0)*132 + k0+kk], a1 = sC[(r0+1)*132 + k0+kk];
                float a2 = sC[(r0+2)*132 + k0+kk], a3 = sC[(r0+3)*132 + k0+kk];
#pragma unroll
                for (int j = 0; j < 16; j++) {
                    acc[0][j] = fmaf(a0, w[j], acc[0][j]);
                    acc[1][j] = fmaf(a1, w[j], acc[1][j]);
                    acc[2][j] = fmaf(a2, w[j], acc[2][j]);
                    acc[3][j] = fmaf(a3, w[j], acc[3][j]);
                }
            }
            __syncthreads();
        }
#pragma unroll
        for (int i = 0; i < 4; i++)
#pragma unroll
            for (int j = 0; j < 16; j++)
                sH[(r0+i)*260 + c0+j] = fmaxf(acc[i][j] + cmb1[c0+j], 0.f);
    }
    __syncthreads();

    // ---- phase C: LayerNorm over 256 cols (4 threads/node) ----
    {
        int node = t >> 2, part = t & 3;
        float s = 0.f, sq = 0.f;
        const float* hrow = sH + node*260 + part*64;
#pragma unroll 16
        for (int i = 0; i < 64; i++) { float v = hrow[i]; s += v; sq += v*v; }
        s  += __shfl_xor_sync(0xffffffffu, s, 1);
        s  += __shfl_xor_sync(0xffffffffu, s, 2);
        sq += __shfl_xor_sync(0xffffffffu, sq, 1);
        sq += __shfl_xor_sync(0xffffffffu, sq, 2);
        float mu = s * (1.f/256.f);
        float var = sq * (1.f/256.f) - mu*mu;
        float rstd = rsqrtf(var + 1e-5f);
        float* hw = sH + node*260 + part*64;
#pragma unroll 16
        for (int i = 0; i < 64; i++) {
            int c = part*64 + i;
            hw[i] = (hw[i] - mu) * rstd * ln_g[c] + ln_b[c];
        }
    }
    __syncthreads();

    // ---- phase D: out = h2n @ cmw2 + cmb2 ----
    {
        const int c2 = tx << 2;
        float acc[4][4];
#pragma unroll
        for (int i = 0; i < 4; i++)
#pragma unroll
            for (int j = 0; j < 4; j++) acc[i][j] = 0.f;
        for (int k0 = 0; k0 < 256; k0 += 16) {
            float4* sWr = (float4*)(sW + ty*68);
            const float4* w4 = (const float4*)(cmw2 + (k0+ty)*YY);
            sWr[tx] = w4[tx];
            __syncthreads();
#pragma unroll
            for (int kk = 0; kk < 16; kk++) {
                float4 w = ((float4*)(sW + kk*68))[tx];
#pragma unroll
                for (int i = 0; i < 4; i++) {
                    float a = sH[(r0+i)*260 + k0+kk];
                    acc[i][0] = fmaf(a, w.x, acc[i][0]);
                    acc[i][1] = fmaf(a, w.y, acc[i][1]);
                    acc[i][2] = fmaf(a, w.z, acc[i][2]);
                    acc[i][3] = fmaf(a, w.w, acc[i][3]);
                }
            }
            __syncthreads();
        }
        float4 b = *(const float4*)(cmb2 + c2);
#pragma unroll
        for (int i = 0; i < 4; i++)
            ((float4*)out)[(n0+r0+i)*16 + tx] =
                make_float4(acc[i][0]+b.x, acc[i][1]+b.y, acc[i][2]+b.z, acc[i][3]+b.w);
    }
}

extern "C" void kernel_launch(void* const* d_in, const int* in_sizes, int n_in,
                              void* d_out, int out_size) {
    const float* x      = (const float*)d_in[0];
    const float* coords = (const float*)d_in[1];
    const float* eattr  = (const float*)d_in[2];
    const int*   eidx   = (const int*)  d_in[3];
    const float* ew1 = (const float*)d_in[4],  *eb1 = (const float*)d_in[5];
    const float* ew2 = (const float*)d_in[6],  *eb2 = (const float*)d_in[7];
    const float* nw1 = (const float*)d_in[8],  *nb1 = (const float*)d_in[9];
    const float* nw2 = (const float*)d_in[10], *nb2 = (const float*)d_in[11];
    const float* wq  = (const float*)d_in[12], *wk  = (const float*)d_in[13];
    const float* wv  = (const float*)d_in[14], *wo  = (const float*)d_in[15];
    const float* cmw1 = (const float*)d_in[16], *cmb1 = (const float*)d_in[17];
    const float* ln_g = (const float*)d_in[18], *ln_b = (const float*)d_in[19];
    const float* cmw2 = (const float*)d_in[20], *cmb2 = (const float*)d_in[21];
    float* out = (float*)d_out;

    cudaFuncSetAttribute(edge_kernel, cudaFuncAttributeMaxDynamicSharedMemorySize, EDGE_SMEM);
    cudaFuncSetAttribute(node_kernel, cudaFuncAttributeMaxDynamicSharedMemorySize, NODE_SMEM);
    cudaFuncSetAttribute(qkv_kernel,  cudaFuncAttributeMaxDynamicSharedMemorySize, QKV_SMEM);
    cudaFuncSetAttribute(comb_kernel, cudaFuncAttributeMaxDynamicSharedMemorySize, CMB_SMEM);

    zero_agg_kernel<<<NN * HH / 4 / 256, 256>>>();
    edge_kernel<<<NE / 64, 256, EDGE_SMEM>>>(x, coords, eattr, eidx, ew1, eb1, ew2, eb2);
    node_kernel<<<NN / 64, 256, NODE_SMEM>>>(x, nw1, nb1, nw2, nb2);
    qkv_kernel<<<dim3(NN / 64, 3), 256, QKV_SMEM>>>(x, wq, wk, wv);
    attn_kernel<<<NN / 64, 256>>>(coords);
    comb_kernel<<<NN / 64, 256, CMB_SMEM>>>(wo, cmw1, cmb1, ln_g, ln_b, cmw2, cmb2, out);
}

// round 4
// speedup vs baseline: 2.2119x; 2.2119x over previous
#include <cuda_runtime.h>
#include <math.h>
#include <stdint.h>

#define NN 8192
#define NE 262144
#define DD 128
#define HH 256
#define DHH 64
#define EDD 16
#define YY 64

__device__ float g_agg[NN * HH];
__device__ float g_xgnn[NN * DD];
__device__ float g_q[NN * DHH];
__device__ float g_k[NN * DHH];
__device__ float g_v[NN * DHH];
__device__ float g_oh[NN * DHH];

__device__ __forceinline__ float silu_f(float v) { return v / (1.0f + __expf(-v)); }

__device__ __forceinline__ float tf32r(float v) {
    uint32_t u;
    asm("cvt.rna.tf32.f32 %0, %1;" : "=r"(u) : "f"(v));
    return __uint_as_float(u);
}

__device__ __forceinline__ void mma8(float d[4], const uint32_t a[4], const uint32_t b[2]) {
    asm volatile("mma.sync.aligned.m16n8k8.row.col.f32.tf32.tf32.f32 "
                 "{%0,%1,%2,%3}, {%4,%5,%6,%7}, {%8,%9}, {%0,%1,%2,%3};\n"
                 : "+f"(d[0]), "+f"(d[1]), "+f"(d[2]), "+f"(d[3])
                 : "r"(a[0]), "r"(a[1]), "r"(a[2]), "r"(a[3]), "r"(b[0]), "r"(b[1]));
}

__device__ __forceinline__ void red2(float* p, float x, float y) {
    asm volatile("red.global.add.v2.f32 [%0], {%1,%2};" :: "l"(p), "f"(x), "f"(y) : "memory");
}

__global__ void zero_agg_kernel() {
    int i = blockIdx.x * blockDim.x + threadIdx.x;
    ((float4*)g_agg)[i] = make_float4(0.f, 0.f, 0.f, 0.f);
}

// =====================================================================
// Edge MLP on tensor cores (tf32 m16n8k8) + segment_sum (red.v2)
// 128 edges/block, 512 threads (16 warps), warp tile 32 rows x 64 cols.
// =====================================================================
#define SA1 292
#define SA2 260
#define SBS 20
#define EDGE_SMEM ((128 * SA1 + 256 * SBS + 256) * 4)

__global__ __launch_bounds__(512, 1) void edge_kernel(
    const float* __restrict__ x, const float* __restrict__ coords,
    const float* __restrict__ eattr, const int* __restrict__ eidx,
    const float* __restrict__ ew1, const float* __restrict__ eb1,
    const float* __restrict__ ew2, const float* __restrict__ eb2)
{
    extern __shared__ float sm[];
    float* sA = sm;                          // [128][292] / [128][260]
    float* sB = sm + 128 * SA1;              // [256][20]
    int* sRow = (int*)(sB + 256 * SBS);
    int* sCol = sRow + 128;

    const int t = threadIdx.x;
    const int lane = t & 31, wid = t >> 5;
    const int rg = wid & 3;
    const int cg = wid >> 2;
    const int e0 = blockIdx.x * 128;
    const int t8 = t >> 8;
    const int nst = t & 255;

    if (t < 128) {
        int e = e0 + t;
        int r = eidx[e], c = eidx[NE + e];
        sRow[t] = r; sCol[t] = c;
        float dx = coords[3*r+0]-coords[3*c+0];
        float dy = coords[3*r+1]-coords[3*c+1];
        float dz = coords[3*r+2]-coords[3*c+2];
        sA[t*SA1 + 256] = tf32r(dx*dx + dy*dy + dz*dz);
    }
    for (int idx = t; idx < 128 * 15; idx += 512) {
        int e = idx / 15, c = idx - e * 15;
        sA[e*SA1 + 273 + c] = 0.f;
    }
    for (int idx = t; idx < 128 * 16; idx += 512) {
        int e = idx >> 4, j = idx & 15;
        sA[e*SA1 + 257 + j] = tf32r(eattr[(e0+e)*EDD + j]);
    }
    __syncthreads();

    const float4* x4 = (const float4*)x;
    for (int idx = t; idx < 128 * 32; idx += 512) {
        int e = idx >> 5, f = idx & 31;
        float4 v = x4[sRow[e]*32 + f];
        v.x = tf32r(v.x); v.y = tf32r(v.y); v.z = tf32r(v.z); v.w = tf32r(v.w);
        ((float4*)(sA + e*SA1))[f] = v;
    }
    for (int idx = t; idx < 128 * 32; idx += 512) {
        int e = idx >> 5, f = idx & 31;
        float4 v = x4[sCol[e]*32 + f];
        v.x = tf32r(v.x); v.y = tf32r(v.y); v.z = tf32r(v.z); v.w = tf32r(v.w);
        ((float4*)(sA + e*SA1 + 128))[f] = v;
    }
    __syncthreads();

    const int arow = rg*32 + (lane >> 2);
    const int brow = cg*64 + (lane >> 2);
    const int kl   = lane & 3;

    float acc[2][8][4];
#pragma unroll
    for (int rf = 0; rf < 2; rf++)
#pragma unroll
        for (int nf = 0; nf < 8; nf++)
#pragma unroll
            for (int j = 0; j < 4; j++) acc[rf][nf][j] = 0.f;

    // ===== layer 1: K = 288 (273 real) =====
    float wreg[8];
#pragma unroll
    for (int i = 0; i < 8; i++) {
        int kg = t8 + 2*i;
        wreg[i] = (kg < 273) ? ew1[kg*HH + nst] : 0.f;
    }
    for (int kb = 0; kb < 18; kb++) {
        __syncthreads();
#pragma unroll
        for (int i = 0; i < 8; i++) sB[nst*SBS + t8 + 2*i] = tf32r(wreg[i]);
        __syncthreads();
        if (kb + 1 < 18) {
            int k0n = (kb + 1) * 16;
#pragma unroll
            for (int i = 0; i < 8; i++) {
                int kg = k0n + t8 + 2*i;
                wreg[i] = (kg < 273) ? ew1[kg*HH + nst] : 0.f;
            }
        }
        int k0 = kb * 16;
#pragma unroll
        for (int ks = 0; ks < 16; ks += 8) {
            const float* ap = sA + arow*SA1 + k0 + ks + kl;
            uint32_t a0[4], a1[4];
            a0[0] = __float_as_uint(ap[0]);
            a0[1] = __float_as_uint(ap[8*SA1]);
            a0[2] = __float_as_uint(ap[4]);
            a0[3] = __float_as_uint(ap[8*SA1 + 4]);
            a1[0] = __float_as_uint(ap[16*SA1]);
            a1[1] = __float_as_uint(ap[24*SA1]);
            a1[2] = __float_as_uint(ap[16*SA1 + 4]);
            a1[3] = __float_as_uint(ap[24*SA1 + 4]);
            const float* bp = sB + brow*SBS + ks + kl;
#pragma unroll
            for (int nf = 0; nf < 8; nf++) {
                uint32_t b[2];
                b[0] = __float_as_uint(bp[nf*8*SBS]);
                b[1] = __float_as_uint(bp[nf*8*SBS + 4]);
                mma8(acc[0][nf], a0, b);
                mma8(acc[1][nf], a1, b);
            }
        }
    }

#pragma unroll
    for (int i = 0; i < 8; i++) wreg[i] = ew2[(t8 + 2*i)*HH + nst];

    __syncthreads();
    float* sH = sm;
    {
        const int row0 = rg*32 + (lane >> 2);
        const int cb = cg*64 + 2*kl;
#pragma unroll
        for (int rf = 0; rf < 2; rf++) {
#pragma unroll
            for (int nf = 0; nf < 8; nf++) {
                int c = cb + nf*8;
                float b0 = eb1[c], b1 = eb1[c+1];
                float2 v0, v1;
                v0.x = tf32r(silu_f(acc[rf][nf][0] + b0));
                v0.y = tf32r(silu_f(acc[rf][nf][1] + b1));
                v1.x = tf32r(silu_f(acc[rf][nf][2] + b0));
                v1.y = tf32r(silu_f(acc[rf][nf][3] + b1));
                *(float2*)(sH + (row0 + rf*16)*SA2 + c)     = v0;
                *(float2*)(sH + (row0 + rf*16 + 8)*SA2 + c) = v1;
            }
        }
    }

#pragma unroll
    for (int rf = 0; rf < 2; rf++)
#pragma unroll
        for (int nf = 0; nf < 8; nf++)
#pragma unroll
            for (int j = 0; j < 4; j++) acc[rf][nf][j] = 0.f;

    // ===== layer 2: K = 256 =====
    for (int kb = 0; kb < 16; kb++) {
        __syncthreads();
#pragma unroll
        for (int i = 0; i < 8; i++) sB[nst*SBS + t8 + 2*i] = tf32r(wreg[i]);
        __syncthreads();
        if (kb + 1 < 16) {
            int k0n = (kb + 1) * 16;
#pragma unroll
            for (int i = 0; i < 8; i++)
                wreg[i] = ew2[(k0n + t8 + 2*i)*HH + nst];
        }
        int k0 = kb * 16;
#pragma unroll
        for (int ks = 0; ks < 16; ks += 8) {
            const float* ap = sH + arow*SA2 + k0 + ks + kl;
            uint32_t a0[4], a1[4];
            a0[0] = __float_as_uint(ap[0]);
            a0[1] = __float_as_uint(ap[8*SA2]);
            a0[2] = __float_as_uint(ap[4]);
            a0[3] = __float_as_uint(ap[8*SA2 + 4]);
            a1[0] = __float_as_uint(ap[16*SA2]);
            a1[1] = __float_as_uint(ap[24*SA2]);
            a1[2] = __float_as_uint(ap[16*SA2 + 4]);
            a1[3] = __float_as_uint(ap[24*SA2 + 4]);
            const float* bp = sB + brow*SBS + ks + kl;
#pragma unroll
            for (int nf = 0; nf < 8; nf++) {
                uint32_t b[2];
                b[0] = __float_as_uint(bp[nf*8*SBS]);
                b[1] = __float_as_uint(bp[nf*8*SBS + 4]);
                mma8(acc[0][nf], a0, b);
                mma8(acc[1][nf], a1, b);
            }
        }
    }

    {
        const int row0 = rg*32 + (lane >> 2);
        const int cb = cg*64 + 2*kl;
#pragma unroll
        for (int rf = 0; rf < 2; rf++) {
            int node0 = sRow[row0 + rf*16];
            int node1 = sRow[row0 + rf*16 + 8];
#pragma unroll
            for (int nf = 0; nf < 8; nf++) {
                int c = cb + nf*8;
                float b0 = eb2[c], b1 = eb2[c+1];
                red2(&g_agg[node0*HH + c], silu_f(acc[rf][nf][0] + b0),
                                           silu_f(acc[rf][nf][1] + b1));
                red2(&g_agg[node1*HH + c], silu_f(acc[rf][nf][2] + b0),
                                           silu_f(acc[rf][nf][3] + b1));
            }
        }
    }
}

// ================= node MLP + residual =================
#define NODE_SMEM ((64 * 388 + 16 * 260) * 4)
__global__ __launch_bounds__(256, 1) void node_kernel(
    const float* __restrict__ x,
    const float* __restrict__ nw1, const float* __restrict__ nb1,
    const float* __restrict__ nw2, const float* __restrict__ nb2)
{
    extern __shared__ float sm[];
    float* sM = sm;
    float* sW = sm + 64 * 388;

    const int t = threadIdx.x, n0 = blockIdx.x * 64;
    const int ty = t >> 4, tx = t & 15, r0 = ty << 2;

    const float4* x4 = (const float4*)x;
    const float4* agg4 = (const float4*)g_agg;
    float4* sM4 = (float4*)sM;
    for (int idx = t; idx < 64*32; idx += 256) {
        int e = idx >> 5, f = idx & 31;
        sM4[e*97 + f] = x4[(n0+e)*32 + f];
    }
    for (int idx = t; idx < 64*64; idx += 256) {
        int e = idx >> 6, f = idx & 63;
        sM4[e*97 + 32 + f] = agg4[(n0+e)*64 + f];
    }
    __syncthreads();

    const int c0 = tx << 4;
    float acc[4][16];
#pragma unroll
    for (int i = 0; i < 4; i++)
#pragma unroll
        for (int j = 0; j < 16; j++) acc[i][j] = 0.f;

    for (int k0 = 0; k0 < 384; k0 += 16) {
        float4* sWr = (float4*)(sW + ty*260);
        const float4* w4 = (const float4*)(nw1 + (k0+ty)*HH);
#pragma unroll
        for (int j = 0; j < 4; j++) sWr[tx*4+j] = w4[tx*4+j];
        __syncthreads();
#pragma unroll
        for (int kk = 0; kk < 16; kk++) {
            float w[16];
            const float4* wp = (const float4*)(sW + kk*260 + c0);
            *((float4*)&w[0]) = wp[0]; *((float4*)&w[4]) = wp[1];
            *((float4*)&w[8]) = wp[2]; *((float4*)&w[12]) = wp[3];
            float a0 = sM[(r0+0)*388 + k0+kk], a1 = sM[(r0+1)*388 + k0+kk];
            float a2 = sM[(r0+2)*388 + k0+kk], a3 = sM[(r0+3)*388 + k0+kk];
#pragma unroll
            for (int j = 0; j < 16; j++) {
                acc[0][j] = fmaf(a0, w[j], acc[0][j]);
                acc[1][j] = fmaf(a1, w[j], acc[1][j]);
                acc[2][j] = fmaf(a2, w[j], acc[2][j]);
                acc[3][j] = fmaf(a3, w[j], acc[3][j]);
            }
        }
        __syncthreads();
    }

    float* sH = sm;
#pragma unroll
    for (int i = 0; i < 4; i++)
#pragma unroll
        for (int j = 0; j < 16; j++)
            sH[(r0+i)*260 + c0+j] = silu_f(acc[i][j] + nb1[c0+j]);
    __syncthreads();

    const int c1 = tx << 3;
    float acc2[4][8];
#pragma unroll
    for (int i = 0; i < 4; i++)
#pragma unroll
        for (int j = 0; j < 8; j++) acc2[i][j] = 0.f;

    for (int k0 = 0; k0 < 256; k0 += 16) {
        float4* sWr = (float4*)(sW + ty*132);
        const float4* w4 = (const float4*)(nw2 + (k0+ty)*DD);
        sWr[tx*2+0] = w4[tx*2+0];
        sWr[tx*2+1] = w4[tx*2+1];
        __syncthreads();
#pragma unroll
        for (int kk = 0; kk < 16; kk++) {
            float w[8];
            const float4* wp = (const float4*)(sW + kk*132 + c1);
            *((float4*)&w[0]) = wp[0]; *((float4*)&w[4]) = wp[1];
            float a0 = sH[(r0+0)*260 + k0+kk], a1 = sH[(r0+1)*260 + k0+kk];
            float a2 = sH[(r0+2)*260 + k0+kk], a3 = sH[(r0+3)*260 + k0+kk];
#pragma unroll
            for (int j = 0; j < 8; j++) {
                acc2[0][j] = fmaf(a0, w[j], acc2[0][j]);
                acc2[1][j] = fmaf(a1, w[j], acc2[1][j]);
                acc2[2][j] = fmaf(a2, w[j], acc2[2][j]);
                acc2[3][j] = fmaf(a3, w[j], acc2[3][j]);
            }
        }
        __syncthreads();
    }

#pragma unroll
    for (int i = 0; i < 4; i++) {
        int node = n0 + r0 + i;
        float4 xa = x4[node*32 + (c1>>2)];
        float4 xb = x4[node*32 + (c1>>2) + 1];
        float4 o0, o1;
        o0.x = acc2[i][0]+nb2[c1+0]+xa.x; o0.y = acc2[i][1]+nb2[c1+1]+xa.y;
        o0.z = acc2[i][2]+nb2[c1+2]+xa.z; o0.w = acc2[i][3]+nb2[c1+3]+xa.w;
        o1.x = acc2[i][4]+nb2[c1+4]+xb.x; o1.y = acc2[i][5]+nb2[c1+5]+xb.y;
        o1.z = acc2[i][6]+nb2[c1+6]+xb.z; o1.w = acc2[i][7]+nb2[c1+7]+xb.w;
        ((float4*)g_xgnn)[node*32 + (c1>>2)]     = o0;
        ((float4*)g_xgnn)[node*32 + (c1>>2) + 1] = o1;
    }
}

// ================= QKV projection =================
#define QKV_SMEM ((64 * 132 + 128 * 68) * 4)
__global__ __launch_bounds__(256, 2) void qkv_kernel(
    const float* __restrict__ x, const float* __restrict__ wq,
    const float* __restrict__ wk, const float* __restrict__ wv)
{
    extern __shared__ float sm[];
    float* sX = sm;
    float* sW = sm + 64 * 132;

    const int t = threadIdx.x, n0 = blockIdx.x * 64;
    const float* w = (blockIdx.y == 0) ? wq : (blockIdx.y == 1) ? wk : wv;
    float* o = (blockIdx.y == 0) ? g_q : (blockIdx.y == 1) ? g_k : g_v;

    const float4* x4 = (const float4*)x;
    float4* sX4 = (float4*)sX;
    for (int idx = t; idx < 64*32; idx += 256) {
        int e = idx >> 5, f = idx & 31;
        sX4[e*33 + f] = x4[(n0+e)*32 + f];
    }
    const float4* w4 = (const float4*)w;
    float4* sW4 = (float4*)sW;
    for (int idx = t; idx < 128*16; idx += 256) {
        int r = idx >> 4, f = idx & 15;
        sW4[r*17 + f] = w4[r*16 + f];
    }
    __syncthreads();

    const int ty = t >> 4, tx = t & 15, r0 = ty << 2;
    float acc[4][4];
#pragma unroll
    for (int i = 0; i < 4; i++)
#pragma unroll
        for (int j = 0; j < 4; j++) acc[i][j] = 0.f;

    for (int k = 0; k < 128; k++) {
        float4 wv4 = sW4[k*17 + tx];
#pragma unroll
        for (int i = 0; i < 4; i++) {
            float a = sX[(r0+i)*132 + k];
            acc[i][0] = fmaf(a, wv4.x, acc[i][0]);
            acc[i][1] = fmaf(a, wv4.y, acc[i][1]);
            acc[i][2] = fmaf(a, wv4.z, acc[i][2]);
            acc[i][3] = fmaf(a, wv4.w, acc[i][3]);
        }
    }
#pragma unroll
    for (int i = 0; i < 4; i++)
        ((float4*)o)[(n0+r0+i)*16 + tx] =
            make_float4(acc[i][0], acc[i][1], acc[i][2], acc[i][3]);
}

// ================= radius-masked flash attention =================
__global__ __launch_bounds__(256) void attn_kernel(const float* __restrict__ coords)
{
    __shared__ float sK[64][68];
    __shared__ float sV[64][68];
    __shared__ float sC[64][4];

    const int t = threadIdx.x;
    const int g = t & 3;
    const int rl = t >> 2;
    const int row = blockIdx.x * 64 + rl;

    float q[16];
    {
        const float4* q4 = (const float4*)(g_q + row*DHH + g*16);
        float4 a = q4[0], b = q4[1], c = q4[2], d = q4[3];
        q[0]=a.x;q[1]=a.y;q[2]=a.z;q[3]=a.w; q[4]=b.x;q[5]=b.y;q[6]=b.z;q[7]=b.w;
        q[8]=c.x;q[9]=c.y;q[10]=c.z;q[11]=c.w; q[12]=d.x;q[13]=d.y;q[14]=d.z;q[15]=d.w;
    }
    const float cx = coords[row*3+0], cy = coords[row*3+1], cz = coords[row*3+2];

    float m = -INFINITY, l = 0.f;
    float o[16];
#pragma unroll
    for (int i = 0; i < 16; i++) o[i] = 0.f;

    for (int j0 = 0; j0 < NN; j0 += 64) {
        for (int idx = t; idx < 64*16; idx += 256) {
            int jj = idx >> 4, f = idx & 15;
            ((float4*)&sK[jj][0])[f] = ((const float4*)g_k)[(j0+jj)*16 + f];
            ((float4*)&sV[jj][0])[f] = ((const float4*)g_v)[(j0+jj)*16 + f];
        }
        {
            int jj = t >> 2, cc = t & 3;
            sC[jj][cc] = (cc < 3) ? coords[(j0+jj)*3 + cc] : 0.f;
        }
        __syncthreads();

        for (int j = 0; j < 64; j++) {
            float dx = cx - sC[j][0], dy = cy - sC[j][1], dz = cz - sC[j][2];
            float d2 = dx*dx + dy*dy + dz*dz;

            const float4* kp = (const float4*)&sK[j][g*16];
            float4 k0 = kp[0], k1 = kp[1], k2 = kp[2], k3 = kp[3];
            float p = q[0]*k0.x+q[1]*k0.y+q[2]*k0.z+q[3]*k0.w
                    + q[4]*k1.x+q[5]*k1.y+q[6]*k1.z+q[7]*k1.w
                    + q[8]*k2.x+q[9]*k2.y+q[10]*k2.z+q[11]*k2.w
                    + q[12]*k3.x+q[13]*k3.y+q[14]*k3.z+q[15]*k3.w;
            p += __shfl_xor_sync(0xffffffffu, p, 1);
            p += __shfl_xor_sync(0xffffffffu, p, 2);

            if (d2 <= 100.0f) {
                float s = p * 0.125f;
                if (s > m) {
                    float corr = __expf(m - s);
                    l *= corr;
#pragma unroll
                    for (int i = 0; i < 16; i++) o[i] *= corr;
                    m = s;
                }
                float w = __expf(s - m);
                l += w;
                const float4* vp = (const float4*)&sV[j][g*16];
                float4 v0 = vp[0], v1 = vp[1], v2 = vp[2], v3 = vp[3];
                o[0]=fmaf(w,v0.x,o[0]); o[1]=fmaf(w,v0.y,o[1]); o[2]=fmaf(w,v0.z,o[2]); o[3]=fmaf(w,v0.w,o[3]);
                o[4]=fmaf(w,v1.x,o[4]); o[5]=fmaf(w,v1.y,o[5]); o[6]=fmaf(w,v1.z,o[6]); o[7]=fmaf(w,v1.w,o[7]);
                o[8]=fmaf(w,v2.x,o[8]); o[9]=fmaf(w,v2.y,o[9]); o[10]=fmaf(w,v2.z,o[10]); o[11]=fmaf(w,v2.w,o[11]);
                o[12]=fmaf(w,v3.x,o[12]); o[13]=fmaf(w,v3.y,o[13]); o[14]=fmaf(w,v3.z,o[14]); o[15]=fmaf(w,v3.w,o[15]);
            }
        }
        __syncthreads();
    }

    float inv = 1.0f / l;
    float4* oh4 = (float4*)(g_oh + row*DHH + g*16);
    oh4[0] = make_float4(o[0]*inv, o[1]*inv, o[2]*inv, o[3]*inv);
    oh4[1] = make_float4(o[4]*inv, o[5]*inv, o[6]*inv, o[7]*inv);
    oh4[2] = make_float4(o[8]*inv, o[9]*inv, o[10]*inv, o[11]*inv);
    oh4[3] = make_float4(o[12]*inv, o[13]*inv, o[14]*inv, o[15]*inv);
}

// ================= combiner =================
#define CMB_SMEM (29248 * 4)
__global__ __launch_bounds__(256, 1) void comb_kernel(
    const float* __restrict__ wo,
    const float* __restrict__ cmw1, const float* __restrict__ cmb1,
    const float* __restrict__ ln_g, const float* __restrict__ ln_b,
    const float* __restrict__ cmw2, const float* __restrict__ cmb2,
    float* __restrict__ out)
{
    extern __shared__ float sm[];
    float* sC = sm;
    float* sH = sm + 8448;
    float* sW = sm + 25088;
    float* sOH = sm + 8448;
    float* sWo = sm + 12800;

    const int t = threadIdx.x, n0 = blockIdx.x * 64;
    const int ty = t >> 4, tx = t & 15, r0 = ty << 2;

    for (int idx = t; idx < 64*16; idx += 256) {
        int e = idx >> 4, f = idx & 15;
        ((float4*)sOH)[e*17 + f] = ((const float4*)g_oh)[(n0+e)*16 + f];
    }
    for (int idx = t; idx < 64*32; idx += 256) {
        int r = idx >> 5, f = idx & 31;
        ((float4*)sWo)[r*33 + f] = ((const float4*)wo)[r*32 + f];
    }
    __syncthreads();

    {
        const int c1 = tx << 3;
        float acc[4][8];
#pragma unroll
        for (int i = 0; i < 4; i++)
#pragma unroll
            for (int j = 0; j < 8; j++) acc[i][j] = 0.f;
        for (int k = 0; k < 64; k++) {
            float4 w0 = ((float4*)sWo)[k*33 + (c1>>2)];
            float4 w1 = ((float4*)sWo)[k*33 + (c1>>2) + 1];
#pragma unroll
            for (int i = 0; i < 4; i++) {
                float a = sOH[(r0+i)*68 + k];
                acc[i][0]=fmaf(a,w0.x,acc[i][0]); acc[i][1]=fmaf(a,w0.y,acc[i][1]);
                acc[i][2]=fmaf(a,w0.z,acc[i][2]); acc[i][3]=fmaf(a,w0.w,acc[i][3]);
                acc[i][4]=fmaf(a,w1.x,acc[i][4]); acc[i][5]=fmaf(a,w1.y,acc[i][5]);
                acc[i][6]=fmaf(a,w1.z,acc[i][6]); acc[i][7]=fmaf(a,w1.w,acc[i][7]);
            }
        }
        __syncthreads();
#pragma unroll
        for (int i = 0; i < 4; i++)
#pragma unroll
            for (int j = 0; j < 8; j++)
                sC[(r0+i)*132 + c1+j] = acc[i][j] + g_xgnn[(n0+r0+i)*128 + c1+j];
    }
    __syncthreads();

    {
        const int c0 = tx << 4;
        float acc[4][16];
#pragma unroll
        for (int i = 0; i < 4; i++)
#pragma unroll
            for (int j = 0; j < 16; j++) acc[i][j] = 0.f;
        for (int k0 = 0; k0 < 128; k0 += 16) {
            float4* sWr = (float4*)(sW + ty*260);
            const float4* w4 = (const float4*)(cmw1 + (k0+ty)*HH);
#pragma unroll
            for (int j = 0; j < 4; j++) sWr[tx*4+j] = w4[tx*4+j];
            __syncthreads();
#pragma unroll
            for (int kk = 0; kk < 16; kk++) {
                float w[16];
                const float4* wp = (const float4*)(sW + kk*260 + c0);
                *((float4*)&w[0]) = wp[0]; *((float4*)&w[4]) = wp[1];
                *((float4*)&w[8]) = wp[2]; *((float4*)&w[12]) = wp[3];
                float a0 = sC[(r0+0)*132 + k0+kk], a1 = sC[(r0+1)*132 + k0+kk];
                float a2 = sC[(r0+2)*132 + k0+kk], a3 = sC[(r0+3)*132 + k0+kk];
#pragma unroll
                for (int j = 0; j < 16; j++) {
                    acc[0][j] = fmaf(a0, w[j], acc[0][j]);
                    acc[1][j] = fmaf(a1, w[j], acc[1][j]);
                    acc[2][j] = fmaf(a2, w[j], acc[2][j]);
                    acc[3][j] = fmaf(a3, w[j], acc[3][j]);
                }
            }
            __syncthreads();
        }
#pragma unroll
        for (int i = 0; i < 4; i++)
#pragma unroll
            for (int j = 0; j < 16; j++)
                sH[(r0+i)*260 + c0+j] = fmaxf(acc[i][j] + cmb1[c0+j], 0.f);
    }
    __syncthreads();

    {
        int node = t >> 2, part = t & 3;
        float s = 0.f, sq = 0.f;
        const float* hrow = sH + node*260 + part*64;
#pragma unroll 16
        for (int i = 0; i < 64; i++) { float v = hrow[i]; s += v; sq += v*v; }
        s  += __shfl_xor_sync(0xffffffffu, s, 1);
        s  += __shfl_xor_sync(0xffffffffu, s, 2);
        sq += __shfl_xor_sync(0xffffffffu, sq, 1);
        sq += __shfl_xor_sync(0xffffffffu, sq, 2);
        float mu = s * (1.f/256.f);
        float var = sq * (1.f/256.f) - mu*mu;
        float rstd = rsqrtf(var + 1e-5f);
        float* hw = sH + node*260 + part*64;
#pragma unroll 16
        for (int i = 0; i < 64; i++) {
            int c = part*64 + i;
            hw[i] = (hw[i] - mu) * rstd * ln_g[c] + ln_b[c];
        }
    }
    __syncthreads();

    {
        const int c2 = tx << 2;
        float acc[4][4];
#pragma unroll
        for (int i = 0; i < 4; i++)
#pragma unroll
            for (int j = 0; j < 4; j++) acc[i][j] = 0.f;
        for (int k0 = 0; k0 < 256; k0 += 16) {
            float4* sWr = (float4*)(sW + ty*68);
            const float4* w4 = (const float4*)(cmw2 + (k0+ty)*YY);
            sWr[tx] = w4[tx];
            __syncthreads();
#pragma unroll
            for (int kk = 0; kk < 16; kk++) {
                float4 w = ((float4*)(sW + kk*68))[tx];
#pragma unroll
                for (int i = 0; i < 4; i++) {
                    float a = sH[(r0+i)*260 + k0+kk];
                    acc[i][0] = fmaf(a, w.x, acc[i][0]);
                    acc[i][1] = fmaf(a, w.y, acc[i][1]);
                    acc[i][2] = fmaf(a, w.z, acc[i][2]);
                    acc[i][3] = fmaf(a, w.w, acc[i][3]);
                }
            }
            __syncthreads();
        }
        float4 b = *(const float4*)(cmb2 + c2);
#pragma unroll
        for (int i = 0; i < 4; i++)
            ((float4*)out)[(n0+r0+i)*16 + tx] =
                make_float4(acc[i][0]+b.x, acc[i][1]+b.y, acc[i][2]+b.z, acc[i][3]+b.w);
    }
}

extern "C" void kernel_launch(void* const* d_in, const int* in_sizes, int n_in,
                              void* d_out, int out_size) {
    const float* x      = (const float*)d_in[0];
    const float* coords = (const float*)d_in[1];
    const float* eattr  = (const float*)d_in[2];
    const int*   eidx   = (const int*)  d_in[3];
    const float* ew1 = (const float*)d_in[4],  *eb1 = (const float*)d_in[5];
    const float* ew2 = (const float*)d_in[6],  *eb2 = (const float*)d_in[7];
    const float* nw1 = (const float*)d_in[8],  *nb1 = (const float*)d_in[9];
    const float* nw2 = (const float*)d_in[10], *nb2 = (const float*)d_in[11];
    const float* wq  = (const float*)d_in[12], *wk  = (const float*)d_in[13];
    const float* wv  = (const float*)d_in[14], *wo  = (const float*)d_in[15];
    const float* cmw1 = (const float*)d_in[16], *cmb1 = (const float*)d_in[17];
    const float* ln_g = (const float*)d_in[18], *ln_b = (const float*)d_in[19];
    const float* cmw2 = (const float*)d_in[20], *cmb2 = (const float*)d_in[21];
    float* out = (float*)d_out;

    cudaFuncSetAttribute(edge_kernel, cudaFuncAttributeMaxDynamicSharedMemorySize, EDGE_SMEM);
    cudaFuncSetAttribute(node_kernel, cudaFuncAttributeMaxDynamicSharedMemorySize, NODE_SMEM);
    cudaFuncSetAttribute(qkv_kernel,  cudaFuncAttributeMaxDynamicSharedMemorySize, QKV_SMEM);
    cudaFuncSetAttribute(comb_kernel, cudaFuncAttributeMaxDynamicSharedMemorySize, CMB_SMEM);

    zero_agg_kernel<<<NN * HH / 4 / 256, 256>>>();
    edge_kernel<<<NE / 128, 512, EDGE_SMEM>>>(x, coords, eattr, eidx, ew1, eb1, ew2, eb2);
    node_kernel<<<NN / 64, 256, NODE_SMEM>>>(x, nw1, nb1, nw2, nb2);
    qkv_kernel<<<dim3(NN / 64, 3), 256, QKV_SMEM>>>(x, wq, wk, wv);
    attn_kernel<<<NN / 64, 256>>>(coords);
    comb_kernel<<<NN / 64, 256, CMB_SMEM>>>(wo, cmw1, cmb1, ln_g, ln_b, cmw2, cmb2, out);
}

// round 5
// speedup vs baseline: 2.9973x; 1.3551x over previous
#include <cuda_runtime.h>
#include <math.h>
#include <stdint.h>

#define NN 8192
#define NE 262144
#define DD 128
#define HH 256
#define DHH 64
#define EDD 16
#define YY 64

__device__ float g_agg[NN * HH];
__device__ float g_xgnn[NN * DD];
__device__ float g_q[NN * DHH];
__device__ float g_k[NN * DHH];
__device__ float g_v[NN * DHH];
__device__ float g_oh[NN * DHH];
__device__ float g_P1[NN * HH];          // x @ ew1[0:128]
__device__ float g_P2[NN * HH];          // x @ ew1[128:256]
__device__ float g_ew2t[HH * HH];        // ew2^T, tf32-rounded  [n][k]
__device__ float g_ew1et[HH * EDD];      // ew1[257:273]^T, tf32-rounded [n][k]
__device__ float g_pm[4 * NN];
__device__ float g_pl[4 * NN];
__device__ float g_po[4 * NN * DHH];

__device__ __forceinline__ float silu_f(float v) { return v / (1.0f + __expf(-v)); }

__device__ __forceinline__ float tf32r(float v) {
    uint32_t u;
    asm("cvt.rna.tf32.f32 %0, %1;" : "=r"(u) : "f"(v));
    return __uint_as_float(u);
}

__device__ __forceinline__ void mma8(float d[4], const uint32_t a[4], const uint32_t b[2]) {
    asm volatile("mma.sync.aligned.m16n8k8.row.col.f32.tf32.tf32.f32 "
                 "{%0,%1,%2,%3}, {%4,%5,%6,%7}, {%8,%9}, {%0,%1,%2,%3};\n"
                 : "+f"(d[0]), "+f"(d[1]), "+f"(d[2]), "+f"(d[3])
                 : "r"(a[0]), "r"(a[1]), "r"(a[2]), "r"(a[3]), "r"(b[0]), "r"(b[1]));
}

__device__ __forceinline__ void red2(float* p, float x, float y) {
    asm volatile("red.global.add.v2.f32 [%0], {%1,%2};" :: "l"(p), "f"(x), "f"(y) : "memory");
}

__device__ __forceinline__ void cpasync16(uint32_t smem_addr, const void* gptr) {
    asm volatile("cp.async.cg.shared.global [%0], [%1], 16;\n" :: "r"(smem_addr), "l"(gptr));
}
__device__ __forceinline__ void cp_commit() { asm volatile("cp.async.commit_group;\n" ::); }
__device__ __forceinline__ void cp_wait0() { asm volatile("cp.async.wait_group 0;\n" ::); }

__global__ void zero_agg_kernel() {
    int i = blockIdx.x * blockDim.x + threadIdx.x;
    ((float4*)g_agg)[i] = make_float4(0.f, 0.f, 0.f, 0.f);
}

// ============ prep: transpose + tf32-round ew2 and ew1[257:273] ============
__global__ void prep_kernel(const float* __restrict__ ew1, const float* __restrict__ ew2) {
    int idx = blockIdx.x * blockDim.x + threadIdx.x;   // 65536 threads
    {
        int n = idx >> 8, k = idx & 255;
        g_ew2t[idx] = tf32r(ew2[k * HH + n]);
    }
    if (idx < HH * EDD) {
        int n = idx >> 4, k = idx & 15;
        g_ew1et[idx] = tf32r(ew1[(257 + k) * HH + n]);
    }
}

// ============ pre: P1 = x@ew1[0:128], P2 = x@ew1[128:256]  (fp32) ============
#define PRE_SMEM ((64 * 132 + 16 * 260) * 4)
__global__ __launch_bounds__(256, 1) void pre_kernel(
    const float* __restrict__ x, const float* __restrict__ ew1)
{
    extern __shared__ float sm[];
    float* sX = sm;                 // [64][132]
    float* sW = sm + 64 * 132;      // [16][260]

    const int t = threadIdx.x, n0 = blockIdx.x * 64;
    const int part = blockIdx.y;
    const float* w = ew1 + part * 128 * HH;
    float* P = (part == 0) ? g_P1 : g_P2;
    const int ty = t >> 4, tx = t & 15, r0 = ty << 2, c0 = tx << 4;

    const float4* x4 = (const float4*)x;
    float4* sX4 = (float4*)sX;
    for (int idx = t; idx < 64 * 32; idx += 256) {
        int e = idx >> 5, f = idx & 31;
        sX4[e * 33 + f] = x4[(n0 + e) * 32 + f];
    }
    __syncthreads();

    float acc[4][16];
#pragma unroll
    for (int i = 0; i < 4; i++)
#pragma unroll
        for (int j = 0; j < 16; j++) acc[i][j] = 0.f;

    for (int k0 = 0; k0 < 128; k0 += 16) {
        float4* sWr = (float4*)(sW + ty * 260);
        const float4* w4 = (const float4*)(w + (k0 + ty) * HH);
#pragma unroll
        for (int j = 0; j < 4; j++) sWr[tx * 4 + j] = w4[tx * 4 + j];
        __syncthreads();
#pragma unroll
        for (int kk = 0; kk < 16; kk++) {
            float wv[16];
            const float4* wp = (const float4*)(sW + kk * 260 + c0);
            *((float4*)&wv[0]) = wp[0]; *((float4*)&wv[4]) = wp[1];
            *((float4*)&wv[8]) = wp[2]; *((float4*)&wv[12]) = wp[3];
            float a0 = sX[(r0 + 0) * 132 + k0 + kk], a1 = sX[(r0 + 1) * 132 + k0 + kk];
            float a2 = sX[(r0 + 2) * 132 + k0 + kk], a3 = sX[(r0 + 3) * 132 + k0 + kk];
#pragma unroll
            for (int j = 0; j < 16; j++) {
                acc[0][j] = fmaf(a0, wv[j], acc[0][j]);
                acc[1][j] = fmaf(a1, wv[j], acc[1][j]);
                acc[2][j] = fmaf(a2, wv[j], acc[2][j]);
                acc[3][j] = fmaf(a3, wv[j], acc[3][j]);
            }
        }
        __syncthreads();
    }
#pragma unroll
    for (int i = 0; i < 4; i++)
#pragma unroll
        for (int j = 0; j < 4; j++)
            ((float4*)P)[(n0 + r0 + i) * 64 + (c0 >> 2) + j] =
                make_float4(acc[i][4*j], acc[i][4*j+1], acc[i][4*j+2], acc[i][4*j+3]);
}

// =====================================================================
// Edge: acc_init = P1[row]+P2[col]+r*wr+eb1; + ea@W_e (tf32, K=16);
// silu; layer2 K=256 tf32 MMA with cp.async double-buffered ew2^T; red.v2
// 128 edges/block, 512 threads, warp tile 32x64.
// =====================================================================
#define SS 260                      // sS/sH row stride (floats)
#define BES 24                      // sBe row stride
#define B2S 24                      // sB2 row stride
#define ATS 20                      // sAttr row stride
#define OFF_SBE   (128 * SS)
#define OFF_SB2   (OFF_SBE + 256 * BES)
#define OFF_SAT   (OFF_SB2 + 2 * 256 * B2S)
#define OFF_RAD   (OFF_SAT + 128 * ATS)
#define OFF_META  (OFF_RAD + 128)
#define EDGE_SMEM ((OFF_META + 256) * 4)

__global__ __launch_bounds__(512, 1) void edge_kernel(
    const float* __restrict__ coords,
    const float* __restrict__ eattr, const int* __restrict__ eidx,
    const float* __restrict__ ew1, const float* __restrict__ eb1,
    const float* __restrict__ eb2)
{
    extern __shared__ float sm[];
    float* sS = sm;                        // [128][260]  (becomes sH)
    float* sBe = sm + OFF_SBE;             // [256][24]
    float* sB2 = sm + OFF_SB2;             // 2 x [256][24]
    float* sAttr = sm + OFF_SAT;           // [128][20]
    float* sRad = sm + OFF_RAD;            // [128]
    int* sRow = (int*)(sm + OFF_META);
    int* sCol = sRow + 128;

    const int t = threadIdx.x;
    const int lane = t & 31, wid = t >> 5;
    const int rg = wid & 3, cg = wid >> 2;
    const int e0 = blockIdx.x * 128;
    const uint32_t sb2_base = (uint32_t)__cvta_generic_to_shared(sB2);

    // kick off layer-2 weight prefetch for kb=0 immediately
    {
        int n = t >> 1, q = t & 1;         // 2 chunks per n via 512 threads? need 4 chunks/n
        // 1024 chunks (256 n x 4 q): thread handles idx=t and t+512
#pragma unroll
        for (int rep = 0; rep < 2; rep++) {
            int idx = t + rep * 512;
            int nn = idx >> 2, qq = idx & 3;
            cpasync16(sb2_base + (nn * B2S + qq * 4) * 4,
                      g_ew2t + nn * HH + 0 * 16 + qq * 4);
        }
        (void)n; (void)q;
    }
    cp_commit();

    // meta + attr + Be staging
    if (t < 128) {
        int e = e0 + t;
        int r = eidx[e], c = eidx[NE + e];
        sRow[t] = r; sCol[t] = c;
        float dx = coords[3*r+0]-coords[3*c+0];
        float dy = coords[3*r+1]-coords[3*c+1];
        float dz = coords[3*r+2]-coords[3*c+2];
        sRad[t] = dx*dx + dy*dy + dz*dz;
    }
    for (int idx = t; idx < 128 * 16; idx += 512) {
        int e = idx >> 4, j = idx & 15;
        sAttr[e * ATS + j] = tf32r(eattr[(e0 + e) * EDD + j]);
    }
    for (int idx = t; idx < 256 * 4; idx += 512) {
        int n = idx >> 2, q = idx & 3;
        *(float4*)(sBe + n * BES + q * 4) = *(const float4*)(g_ew1et + n * EDD + q * 4);
    }
    __syncthreads();

    // S = P1[row] + P2[col] + rad*wr + eb1
    {
        const float4* P1_4 = (const float4*)g_P1;
        const float4* P2_4 = (const float4*)g_P2;
        const float4* WR4 = (const float4*)(ew1 + 256 * HH);
        const float4* B14 = (const float4*)eb1;
        for (int idx = t; idx < 128 * 64; idx += 512) {
            int e = idx >> 6, f = idx & 63;
            float4 p1 = P1_4[sRow[e] * 64 + f];
            float4 p2 = P2_4[sCol[e] * 64 + f];
            float4 wr = WR4[f], bb = B14[f];
            float rad = sRad[e];
            float4 s;
            s.x = p1.x + p2.x + rad * wr.x + bb.x;
            s.y = p1.y + p2.y + rad * wr.y + bb.y;
            s.z = p1.z + p2.z + rad * wr.z + bb.z;
            s.w = p1.w + p2.w + rad * wr.w + bb.w;
            *(float4*)(sS + e * SS + f * 4) = s;
        }
    }
    __syncthreads();

    const int arow = rg * 32 + (lane >> 2);
    const int brow = cg * 64 + (lane >> 2);
    const int kl = lane & 3;
    const int g = lane >> 2;
    const int cb = cg * 64 + 2 * kl;

    // acc init from sS (warp-private tile)
    float acc[2][8][4];
#pragma unroll
    for (int rf = 0; rf < 2; rf++) {
        int rbase = rg * 32 + rf * 16 + g;
#pragma unroll
        for (int nf = 0; nf < 8; nf++) {
            int c = cb + nf * 8;
            float2 v0 = *(const float2*)(sS + rbase * SS + c);
            float2 v1 = *(const float2*)(sS + (rbase + 8) * SS + c);
            acc[rf][nf][0] = v0.x; acc[rf][nf][1] = v0.y;
            acc[rf][nf][2] = v1.x; acc[rf][nf][3] = v1.y;
        }
    }

    // layer-1 edge-attr MMA: K=16
#pragma unroll
    for (int ks = 0; ks < 16; ks += 8) {
        const float* ap = sAttr + arow * ATS + ks + kl;
        uint32_t a0[4], a1[4];
        a0[0] = __float_as_uint(ap[0]);
        a0[1] = __float_as_uint(ap[8 * ATS]);
        a0[2] = __float_as_uint(ap[4]);
        a0[3] = __float_as_uint(ap[8 * ATS + 4]);
        a1[0] = __float_as_uint(ap[16 * ATS]);
        a1[1] = __float_as_uint(ap[24 * ATS]);
        a1[2] = __float_as_uint(ap[16 * ATS + 4]);
        a1[3] = __float_as_uint(ap[24 * ATS + 4]);
        const float* bp = sBe + brow * BES + ks + kl;
#pragma unroll
        for (int nf = 0; nf < 8; nf++) {
            uint32_t b[2];
            b[0] = __float_as_uint(bp[nf * 8 * BES]);
            b[1] = __float_as_uint(bp[nf * 8 * BES + 4]);
            mma8(acc[0][nf], a0, b);
            mma8(acc[1][nf], a1, b);
        }
    }

    // epilogue 1: silu + tf32 round -> sH (aliases sS; warp-private tile)
    float* sH = sS;
    {
        const int row0 = rg * 32 + g;
#pragma unroll
        for (int rf = 0; rf < 2; rf++) {
#pragma unroll
            for (int nf = 0; nf < 8; nf++) {
                int c = cb + nf * 8;
                float2 v0, v1;
                v0.x = tf32r(silu_f(acc[rf][nf][0]));
                v0.y = tf32r(silu_f(acc[rf][nf][1]));
                v1.x = tf32r(silu_f(acc[rf][nf][2]));
                v1.y = tf32r(silu_f(acc[rf][nf][3]));
                *(float2*)(sH + (row0 + rf * 16) * SS + c)     = v0;
                *(float2*)(sH + (row0 + rf * 16 + 8) * SS + c) = v1;
            }
        }
    }

#pragma unroll
    for (int rf = 0; rf < 2; rf++)
#pragma unroll
        for (int nf = 0; nf < 8; nf++)
#pragma unroll
            for (int j = 0; j < 4; j++) acc[rf][nf][j] = 0.f;

    // layer 2: K=256, 16 k-blocks, cp.async double buffer, one sync/kb
    for (int kb = 0; kb < 16; kb++) {
        cp_wait0();
        __syncthreads();
        if (kb + 1 < 16) {
            int koff = (kb + 1) * 16;
            uint32_t dstb = sb2_base + (((kb + 1) & 1) * 256 * B2S) * 4;
#pragma unroll
            for (int rep = 0; rep < 2; rep++) {
                int idx = t + rep * 512;
                int nn = idx >> 2, qq = idx & 3;
                cpasync16(dstb + (nn * B2S + qq * 4) * 4,
                          g_ew2t + nn * HH + koff + qq * 4);
            }
            cp_commit();
        }
        const float* bufB = sB2 + (kb & 1) * 256 * B2S;
        int k0 = kb * 16;
#pragma unroll
        for (int ks = 0; ks < 16; ks += 8) {
            const float* ap = sH + arow * SS + k0 + ks + kl;
            uint32_t a0[4], a1[4];
            a0[0] = __float_as_uint(ap[0]);
            a0[1] = __float_as_uint(ap[8 * SS]);
            a0[2] = __float_as_uint(ap[4]);
            a0[3] = __float_as_uint(ap[8 * SS + 4]);
            a1[0] = __float_as_uint(ap[16 * SS]);
            a1[1] = __float_as_uint(ap[24 * SS]);
            a1[2] = __float_as_uint(ap[16 * SS + 4]);
            a1[3] = __float_as_uint(ap[24 * SS + 4]);
            const float* bp = bufB + brow * B2S + ks + kl;
#pragma unroll
            for (int nf = 0; nf < 8; nf++) {
                uint32_t b[2];
                b[0] = __float_as_uint(bp[nf * 8 * B2S]);
                b[1] = __float_as_uint(bp[nf * 8 * B2S + 4]);
                mma8(acc[0][nf], a0, b);
                mma8(acc[1][nf], a1, b);
            }
        }
    }

    // epilogue 2: silu + segment-sum
    {
        const int row0 = rg * 32 + g;
#pragma unroll
        for (int rf = 0; rf < 2; rf++) {
            int node0 = sRow[row0 + rf * 16];
            int node1 = sRow[row0 + rf * 16 + 8];
#pragma unroll
            for (int nf = 0; nf < 8; nf++) {
                int c = cb + nf * 8;
                float b0 = eb2[c], b1 = eb2[c + 1];
                red2(&g_agg[node0 * HH + c], silu_f(acc[rf][nf][0] + b0),
                                             silu_f(acc[rf][nf][1] + b1));
                red2(&g_agg[node1 * HH + c], silu_f(acc[rf][nf][2] + b0),
                                             silu_f(acc[rf][nf][3] + b1));
            }
        }
    }
}

// ================= node MLP + residual =================
#define NODE_SMEM ((64 * 388 + 16 * 260) * 4)
__global__ __launch_bounds__(256, 1) void node_kernel(
    const float* __restrict__ x,
    const float* __restrict__ nw1, const float* __restrict__ nb1,
    const float* __restrict__ nw2, const float* __restrict__ nb2)
{
    extern __shared__ float sm[];
    float* sM = sm;
    float* sW = sm + 64 * 388;

    const int t = threadIdx.x, n0 = blockIdx.x * 64;
    const int ty = t >> 4, tx = t & 15, r0 = ty << 2;

    const float4* x4 = (const float4*)x;
    const float4* agg4 = (const float4*)g_agg;
    float4* sM4 = (float4*)sM;
    for (int idx = t; idx < 64*32; idx += 256) {
        int e = idx >> 5, f = idx & 31;
        sM4[e*97 + f] = x4[(n0+e)*32 + f];
    }
    for (int idx = t; idx < 64*64; idx += 256) {
        int e = idx >> 6, f = idx & 63;
        sM4[e*97 + 32 + f] = agg4[(n0+e)*64 + f];
    }
    __syncthreads();

    const int c0 = tx << 4;
    float acc[4][16];
#pragma unroll
    for (int i = 0; i < 4; i++)
#pragma unroll
        for (int j = 0; j < 16; j++) acc[i][j] = 0.f;

    for (int k0 = 0; k0 < 384; k0 += 16) {
        float4* sWr = (float4*)(sW + ty*260);
        const float4* w4 = (const float4*)(nw1 + (k0+ty)*HH);
#pragma unroll
        for (int j = 0; j < 4; j++) sWr[tx*4+j] = w4[tx*4+j];
        __syncthreads();
#pragma unroll
        for (int kk = 0; kk < 16; kk++) {
            float w[16];
            const float4* wp = (const float4*)(sW + kk*260 + c0);
            *((float4*)&w[0]) = wp[0]; *((float4*)&w[4]) = wp[1];
            *((float4*)&w[8]) = wp[2]; *((float4*)&w[12]) = wp[3];
            float a0 = sM[(r0+0)*388 + k0+kk], a1 = sM[(r0+1)*388 + k0+kk];
            float a2 = sM[(r0+2)*388 + k0+kk], a3 = sM[(r0+3)*388 + k0+kk];
#pragma unroll
            for (int j = 0; j < 16; j++) {
                acc[0][j] = fmaf(a0, w[j], acc[0][j]);
                acc[1][j] = fmaf(a1, w[j], acc[1][j]);
                acc[2][j] = fmaf(a2, w[j], acc[2][j]);
                acc[3][j] = fmaf(a3, w[j], acc[3][j]);
            }
        }
        __syncthreads();
    }

    float* sH = sm;
#pragma unroll
    for (int i = 0; i < 4; i++)
#pragma unroll
        for (int j = 0; j < 16; j++)
            sH[(r0+i)*260 + c0+j] = silu_f(acc[i][j] + nb1[c0+j]);
    __syncthreads();

    const int c1 = tx << 3;
    float acc2[4][8];
#pragma unroll
    for (int i = 0; i < 4; i++)
#pragma unroll
        for (int j = 0; j < 8; j++) acc2[i][j] = 0.f;

    for (int k0 = 0; k0 < 256; k0 += 16) {
        float4* sWr = (float4*)(sW + ty*132);
        const float4* w4 = (const float4*)(nw2 + (k0+ty)*DD);
        sWr[tx*2+0] = w4[tx*2+0];
        sWr[tx*2+1] = w4[tx*2+1];
        __syncthreads();
#pragma unroll
        for (int kk = 0; kk < 16; kk++) {
            float w[8];
            const float4* wp = (const float4*)(sW + kk*132 + c1);
            *((float4*)&w[0]) = wp[0]; *((float4*)&w[4]) = wp[1];
            float a0 = sH[(r0+0)*260 + k0+kk], a1 = sH[(r0+1)*260 + k0+kk];
            float a2 = sH[(r0+2)*260 + k0+kk], a3 = sH[(r0+3)*260 + k0+kk];
#pragma unroll
            for (int j = 0; j < 8; j++) {
                acc2[0][j] = fmaf(a0, w[j], acc2[0][j]);
                acc2[1][j] = fmaf(a1, w[j], acc2[1][j]);
                acc2[2][j] = fmaf(a2, w[j], acc2[2][j]);
                acc2[3][j] = fmaf(a3, w[j], acc2[3][j]);
            }
        }
        __syncthreads();
    }

#pragma unroll
    for (int i = 0; i < 4; i++) {
        int node = n0 + r0 + i;
        float4 xa = x4[node*32 + (c1>>2)];
        float4 xb = x4[node*32 + (c1>>2) + 1];
        float4 o0, o1;
        o0.x = acc2[i][0]+nb2[c1+0]+xa.x; o0.y = acc2[i][1]+nb2[c1+1]+xa.y;
        o0.z = acc2[i][2]+nb2[c1+2]+xa.z; o0.w = acc2[i][3]+nb2[c1+3]+xa.w;
        o1.x = acc2[i][4]+nb2[c1+4]+xb.x; o1.y = acc2[i][5]+nb2[c1+5]+xb.y;
        o1.z = acc2[i][6]+nb2[c1+6]+xb.z; o1.w = acc2[i][7]+nb2[c1+7]+xb.w;
        ((float4*)g_xgnn)[node*32 + (c1>>2)]     = o0;
        ((float4*)g_xgnn)[node*32 + (c1>>2) + 1] = o1;
    }
}

// ================= QKV projection =================
#define QKV_SMEM ((64 * 132 + 128 * 68) * 4)
__global__ __launch_bounds__(256, 2) void qkv_kernel(
    const float* __restrict__ x, const float* __restrict__ wq,
    const float* __restrict__ wk, const float* __restrict__ wv)
{
    extern __shared__ float sm[];
    float* sX = sm;
    float* sW = sm + 64 * 132;

    const int t = threadIdx.x, n0 = blockIdx.x * 64;
    const float* w = (blockIdx.y == 0) ? wq : (blockIdx.y == 1) ? wk : wv;
    float* o = (blockIdx.y == 0) ? g_q : (blockIdx.y == 1) ? g_k : g_v;

    const float4* x4 = (const float4*)x;
    float4* sX4 = (float4*)sX;
    for (int idx = t; idx < 64*32; idx += 256) {
        int e = idx >> 5, f = idx & 31;
        sX4[e*33 + f] = x4[(n0+e)*32 + f];
    }
    const float4* w4 = (const float4*)w;
    float4* sW4 = (float4*)sW;
    for (int idx = t; idx < 128*16; idx += 256) {
        int r = idx >> 4, f = idx & 15;
        sW4[r*17 + f] = w4[r*16 + f];
    }
    __syncthreads();

    const int ty = t >> 4, tx = t & 15, r0 = ty << 2;
    float acc[4][4];
#pragma unroll
    for (int i = 0; i < 4; i++)
#pragma unroll
        for (int j = 0; j < 4; j++) acc[i][j] = 0.f;

    for (int k = 0; k < 128; k++) {
        float4 wv4 = sW4[k*17 + tx];
#pragma unroll
        for (int i = 0; i < 4; i++) {
            float a = sX[(r0+i)*132 + k];
            acc[i][0] = fmaf(a, wv4.x, acc[i][0]);
            acc[i][1] = fmaf(a, wv4.y, acc[i][1]);
            acc[i][2] = fmaf(a, wv4.z, acc[i][2]);
            acc[i][3] = fmaf(a, wv4.w, acc[i][3]);
        }
    }
#pragma unroll
    for (int i = 0; i < 4; i++)
        ((float4*)o)[(n0+r0+i)*16 + tx] =
            make_float4(acc[i][0], acc[i][1], acc[i][2], acc[i][3]);
}

// ================= radius-masked flash attention (split-j x4) =================
__global__ __launch_bounds__(256) void attn_kernel(const float* __restrict__ coords)
{
    __shared__ float sK[64][68];
    __shared__ float sV[64][68];
    __shared__ float sC[64][4];

    const int t = threadIdx.x;
    const int g = t & 3;
    const int rl = t >> 2;
    const int row = blockIdx.x * 64 + rl;
    const int split = blockIdx.y;

    float q[16];
    {
        const float4* q4 = (const float4*)(g_q + row*DHH + g*16);
        float4 a = q4[0], b = q4[1], c = q4[2], d = q4[3];
        q[0]=a.x;q[1]=a.y;q[2]=a.z;q[3]=a.w; q[4]=b.x;q[5]=b.y;q[6]=b.z;q[7]=b.w;
        q[8]=c.x;q[9]=c.y;q[10]=c.z;q[11]=c.w; q[12]=d.x;q[13]=d.y;q[14]=d.z;q[15]=d.w;
    }
    const float cx = coords[row*3+0], cy = coords[row*3+1], cz = coords[row*3+2];

    float m = -INFINITY, l = 0.f;
    float o[16];
#pragma unroll
    for (int i = 0; i < 16; i++) o[i] = 0.f;

    const int jbeg = split * (NN / 4), jend = jbeg + NN / 4;
    for (int j0 = jbeg; j0 < jend; j0 += 64) {
        for (int idx = t; idx < 64*16; idx += 256) {
            int jj = idx >> 4, f = idx & 15;
            ((float4*)&sK[jj][0])[f] = ((const float4*)g_k)[(j0+jj)*16 + f];
            ((float4*)&sV[jj][0])[f] = ((const float4*)g_v)[(j0+jj)*16 + f];
        }
        {
            int jj = t >> 2, cc = t & 3;
            sC[jj][cc] = (cc < 3) ? coords[(j0+jj)*3 + cc] : 0.f;
        }
        __syncthreads();

        for (int j = 0; j < 64; j++) {
            float dx = cx - sC[j][0], dy = cy - sC[j][1], dz = cz - sC[j][2];
            float d2 = dx*dx + dy*dy + dz*dz;

            const float4* kp = (const float4*)&sK[j][g*16];
            float4 k0 = kp[0], k1 = kp[1], k2 = kp[2], k3 = kp[3];
            float p = q[0]*k0.x+q[1]*k0.y+q[2]*k0.z+q[3]*k0.w
                    + q[4]*k1.x+q[5]*k1.y+q[6]*k1.z+q[7]*k1.w
                    + q[8]*k2.x+q[9]*k2.y+q[10]*k2.z+q[11]*k2.w
                    + q[12]*k3.x+q[13]*k3.y+q[14]*k3.z+q[15]*k3.w;
            p += __shfl_xor_sync(0xffffffffu, p, 1);
            p += __shfl_xor_sync(0xffffffffu, p, 2);

            if (d2 <= 100.0f) {
                float s = p * 0.125f;
                if (s > m) {
                    float corr = __expf(m - s);
                    l *= corr;
#pragma unroll
                    for (int i = 0; i < 16; i++) o[i] *= corr;
                    m = s;
                }
                float w = __expf(s - m);
                l += w;
                const float4* vp = (const float4*)&sV[j][g*16];
                float4 v0 = vp[0], v1 = vp[1], v2 = vp[2], v3 = vp[3];
                o[0]=fmaf(w,v0.x,o[0]); o[1]=fmaf(w,v0.y,o[1]); o[2]=fmaf(w,v0.z,o[2]); o[3]=fmaf(w,v0.w,o[3]);
                o[4]=fmaf(w,v1.x,o[4]); o[5]=fmaf(w,v1.y,o[5]); o[6]=fmaf(w,v1.z,o[6]); o[7]=fmaf(w,v1.w,o[7]);
                o[8]=fmaf(w,v2.x,o[8]); o[9]=fmaf(w,v2.y,o[9]); o[10]=fmaf(w,v2.z,o[10]); o[11]=fmaf(w,v2.w,o[11]);
                o[12]=fmaf(w,v3.x,o[12]); o[13]=fmaf(w,v3.y,o[13]); o[14]=fmaf(w,v3.z,o[14]); o[15]=fmaf(w,v3.w,o[15]);
            }
        }
        __syncthreads();
    }

    float4* po4 = (float4*)(g_po + (split * NN + row) * DHH + g * 16);
    po4[0] = make_float4(o[0], o[1], o[2], o[3]);
    po4[1] = make_float4(o[4], o[5], o[6], o[7]);
    po4[2] = make_float4(o[8], o[9], o[10], o[11]);
    po4[3] = make_float4(o[12], o[13], o[14], o[15]);
    if (g == 0) {
        g_pm[split * NN + row] = m;
        g_pl[split * NN + row] = l;
    }
}

__global__ __launch_bounds__(256) void attn_combine_kernel()
{
    int tg = blockIdx.x * 256 + threadIdx.x;   // 32768 threads: (row, 16-dim group)
    int row = tg >> 2, grp = (tg & 3) * 4;     // grp in float4 units (4 float4 = 16 dims)
    float m0 = g_pm[row], m1 = g_pm[NN + row], m2 = g_pm[2*NN + row], m3 = g_pm[3*NN + row];
    float M = fmaxf(fmaxf(m0, m1), fmaxf(m2, m3));
    float w0 = __expf(m0 - M), w1 = __expf(m1 - M), w2 = __expf(m2 - M), w3 = __expf(m3 - M);
    float L = w0 * g_pl[row] + w1 * g_pl[NN + row] + w2 * g_pl[2*NN + row] + w3 * g_pl[3*NN + row];
    float inv = 1.0f / L;
    const float4* po = (const float4*)g_po;
#pragma unroll
    for (int qq = 0; qq < 4; qq++) {
        float4 a = po[(0*NN + row) * 16 + grp + qq];
        float4 b = po[(1*NN + row) * 16 + grp + qq];
        float4 c = po[(2*NN + row) * 16 + grp + qq];
        float4 d = po[(3*NN + row) * 16 + grp + qq];
        float4 r;
        r.x = (w0*a.x + w1*b.x + w2*c.x + w3*d.x) * inv;
        r.y = (w0*a.y + w1*b.y + w2*c.y + w3*d.y) * inv;
        r.z = (w0*a.z + w1*b.z + w2*c.z + w3*d.z) * inv;
        r.w = (w0*a.w + w1*b.w + w2*c.w + w3*d.w) * inv;
        ((float4*)g_oh)[row * 16 + grp + qq] = r;
    }
}

// ================= combiner =================
#define CMB_SMEM (29248 * 4)
__global__ __launch_bounds__(256, 1) void comb_kernel(
    const float* __restrict__ wo,
    const float* __restrict__ cmw1, const float* __restrict__ cmb1,
    const float* __restrict__ ln_g, const float* __restrict__ ln_b,
    const float* __restrict__ cmw2, const float* __restrict__ cmb2,
    float* __restrict__ out)
{
    extern __shared__ float sm[];
    float* sC = sm;
    float* sH = sm + 8448;
    float* sW = sm + 25088;
    float* sOH = sm + 8448;
    float* sWo = sm + 12800;

    const int t = threadIdx.x, n0 = blockIdx.x * 64;
    const int ty = t >> 4, tx = t & 15, r0 = ty << 2;

    for (int idx = t; idx < 64*16; idx += 256) {
        int e = idx >> 4, f = idx & 15;
        ((float4*)sOH)[e*17 + f] = ((const float4*)g_oh)[(n0+e)*16 + f];
    }
    for (int idx = t; idx < 64*32; idx += 256) {
        int r = idx >> 5, f = idx & 31;
        ((float4*)sWo)[r*33 + f] = ((const float4*)wo)[r*32 + f];
    }
    __syncthreads();

    {
        const int c1 = tx << 3;
        float acc[4][8];
#pragma unroll
        for (int i = 0; i < 4; i++)
#pragma unroll
            for (int j = 0; j < 8; j++) acc[i][j] = 0.f;
        for (int k = 0; k < 64; k++) {
            float4 w0 = ((float4*)sWo)[k*33 + (c1>>2)];
            float4 w1 = ((float4*)sWo)[k*33 + (c1>>2) + 1];
#pragma unroll
            for (int i = 0; i < 4; i++) {
                float a = sOH[(r0+i)*68 + k];
                acc[i][0]=fmaf(a,w0.x,acc[i][0]); acc[i][1]=fmaf(a,w0.y,acc[i][1]);
                acc[i][2]=fmaf(a,w0.z,acc[i][2]); acc[i][3]=fmaf(a,w0.w,acc[i][3]);
                acc[i][4]=fmaf(a,w1.x,acc[i][4]); acc[i][5]=fmaf(a,w1.y,acc[i][5]);
                acc[i][6]=fmaf(a,w1.z,acc[i][6]); acc[i][7]=fmaf(a,w1.w,acc[i][7]);
            }
        }
        __syncthreads();
#pragma unroll
        for (int i = 0; i < 4; i++)
#pragma unroll
            for (int j = 0; j < 8; j++)
                sC[(r0+i)*132 + c1+j] = acc[i][j] + g_xgnn[(n0+r0+i)*128 + c1+j];
    }
    __syncthreads();

    {
        const int c0 = tx << 4;
        float acc[4][16];
#pragma unroll
        for (int i = 0; i < 4; i++)
#pragma unroll
            for (int j = 0; j < 16; j++) acc[i][j] = 0.f;
        for (int k0 = 0; k0 < 128; k0 += 16) {
            float4* sWr = (float4*)(sW + ty*260);
            const float4* w4 = (const float4*)(cmw1 + (k0+ty)*HH);
#pragma unroll
            for (int j = 0; j < 4; j++) sWr[tx*4+j] = w4[tx*4+j];
            __syncthreads();
#pragma unroll
            for (int kk = 0; kk < 16; kk++) {
                float w[16];
                const float4* wp = (const float4*)(sW + kk*260 + c0);
                *((float4*)&w[0]) = wp[0]; *((float4*)&w[4]) = wp[1];
                *((float4*)&w[8]) = wp[2]; *((float4*)&w[12]) = wp[3];
                float a0 = sC[(r0+0)*132 + k0+kk], a1 = sC[(r0+1)*132 + k0+kk];
                float a2 = sC[(r0+2)*132 + k0+kk], a3 = sC[(r0+3)*132 + k0+kk];
#pragma unroll
                for (int j = 0; j < 16; j++) {
                    acc[0][j] = fmaf(a0, w[j], acc[0][j]);
                    acc[1][j] = fmaf(a1, w[j], acc[1][j]);
                    acc[2][j] = fmaf(a2, w[j], acc[2][j]);
                    acc[3][j] = fmaf(a3, w[j], acc[3][j]);
                }
            }
            __syncthreads();
        }
#pragma unroll
        for (int i = 0; i < 4; i++)
#pragma unroll
            for (int j = 0; j < 16; j++)
                sH[(r0+i)*260 + c0+j] = fmaxf(acc[i][j] + cmb1[c0+j], 0.f);
    }
    __syncthreads();

    {
        int node = t >> 2, part = t & 3;
        float s = 0.f, sq = 0.f;
        const float* hrow = sH + node*260 + part*64;
#pragma unroll 16
        for (int i = 0; i < 64; i++) { float v = hrow[i]; s += v; sq += v*v; }
        s  += __shfl_xor_sync(0xffffffffu, s, 1);
        s  += __shfl_xor_sync(0xffffffffu, s, 2);
        sq += __shfl_xor_sync(0xffffffffu, sq, 1);
        sq += __shfl_xor_sync(0xffffffffu, sq, 2);
        float mu = s * (1.f/256.f);
        float var = sq * (1.f/256.f) - mu*mu;
        float rstd = rsqrtf(var + 1e-5f);
        float* hw = sH + node*260 + part*64;
#pragma unroll 16
        for (int i = 0; i < 64; i++) {
            int c = part*64 + i;
            hw[i] = (hw[i] - mu) * rstd * ln_g[c] + ln_b[c];
        }
    }
    __syncthreads();

    {
        const int c2 = tx << 2;
        float acc[4][4];
#pragma unroll
        for (int i = 0; i < 4; i++)
#pragma unroll
            for (int j = 0; j < 4; j++) acc[i][j] = 0.f;
        for (int k0 = 0; k0 < 256; k0 += 16) {
            float4* sWr = (float4*)(sW + ty*68);
            const float4* w4 = (const float4*)(cmw2 + (k0+ty)*YY);
            sWr[tx] = w4[tx];
            __syncthreads();
#pragma unroll
            for (int kk = 0; kk < 16; kk++) {
                float4 w = ((float4*)(sW + kk*68))[tx];
#pragma unroll
                for (int i = 0; i < 4; i++) {
                    float a = sH[(r0+i)*260 + k0+kk];
                    acc[i][0] = fmaf(a, w.x, acc[i][0]);
                    acc[i][1] = fmaf(a, w.y, acc[i][1]);
                    acc[i][2] = fmaf(a, w.z, acc[i][2]);
                    acc[i][3] = fmaf(a, w.w, acc[i][3]);
                }
            }
            __syncthreads();
        }
        float4 b = *(const float4*)(cmb2 + c2);
#pragma unroll
        for (int i = 0; i < 4; i++)
            ((float4*)out)[(n0+r0+i)*16 + tx] =
                make_float4(acc[i][0]+b.x, acc[i][1]+b.y, acc[i][2]+b.z, acc[i][3]+b.w);
    }
}

extern "C" void kernel_launch(void* const* d_in, const int* in_sizes, int n_in,
                              void* d_out, int out_size) {
    const float* x      = (const float*)d_in[0];
    const float* coords = (const float*)d_in[1];
    const float* eattr  = (const float*)d_in[2];
    const int*   eidx   = (const int*)  d_in[3];
    const float* ew1 = (const float*)d_in[4],  *eb1 = (const float*)d_in[5];
    const float* ew2 = (const float*)d_in[6],  *eb2 = (const float*)d_in[7];
    const float* nw1 = (const float*)d_in[8],  *nb1 = (const float*)d_in[9];
    const float* nw2 = (const float*)d_in[10], *nb2 = (const float*)d_in[11];
    const float* wq  = (const float*)d_in[12], *wk  = (const float*)d_in[13];
    const float* wv  = (const float*)d_in[14], *wo  = (const float*)d_in[15];
    const float* cmw1 = (const float*)d_in[16], *cmb1 = (const float*)d_in[17];
    const float* ln_g = (const float*)d_in[18], *ln_b = (const float*)d_in[19];
    const float* cmw2 = (const float*)d_in[20], *cmb2 = (const float*)d_in[21];
    float* out = (float*)d_out;

    cudaFuncSetAttribute(pre_kernel,  cudaFuncAttributeMaxDynamicSharedMemorySize, PRE_SMEM);
    cudaFuncSetAttribute(edge_kernel, cudaFuncAttributeMaxDynamicSharedMemorySize, EDGE_SMEM);
    cudaFuncSetAttribute(node_kernel, cudaFuncAttributeMaxDynamicSharedMemorySize, NODE_SMEM);
    cudaFuncSetAttribute(qkv_kernel,  cudaFuncAttributeMaxDynamicSharedMemorySize, QKV_SMEM);
    cudaFuncSetAttribute(comb_kernel, cudaFuncAttributeMaxDynamicSharedMemorySize, CMB_SMEM);

    prep_kernel<<<256, 256>>>(ew1, ew2);
    pre_kernel<<<dim3(NN / 64, 2), 256, PRE_SMEM>>>(x, ew1);
    zero_agg_kernel<<<NN * HH / 4 / 256, 256>>>();
    edge_kernel<<<NE / 128, 512, EDGE_SMEM>>>(coords, eattr, eidx, ew1, eb1, eb2);
    node_kernel<<<NN / 64, 256, NODE_SMEM>>>(x, nw1, nb1, nw2, nb2);
    qkv_kernel<<<dim3(NN / 64, 3), 256, QKV_SMEM>>>(x, wq, wk, wv);
    attn_kernel<<<dim3(NN / 64, 4), 256>>>(coords);
    attn_combine_kernel<<<NN * 4 / 256, 256>>>();
    comb_kernel<<<NN / 64, 256, CMB_SMEM>>>(wo, cmw1, cmb1, ln_g, ln_b, cmw2, cmb2, out);
}

// round 6
// speedup vs baseline: 6.3581x; 2.1212x over previous
#include <cuda_runtime.h>
#include <math.h>
#include <stdint.h>

#define NN 8192
#define NE 262144
#define DD 128
#define HH 256
#define DHH 64
#define EDD 16
#define YY 64

__device__ float g_agg[NN * HH];
__device__ float g_xgnn[NN * DD];
__device__ float g_q[NN * DHH];
__device__ float g_k[NN * DHH];          // tf32-rounded at qkv
__device__ float g_vt[DHH * NN];         // V^T, tf32-rounded
__device__ float g_oh[NN * DHH];
__device__ float g_P1[NN * HH];
__device__ float g_P2[NN * HH];
__device__ float g_ew2t[HH * HH];
__device__ float g_ew1et[HH * EDD];
__device__ float g_pm[4 * NN];
__device__ float g_pl[4 * NN];
__device__ float g_po[4 * NN * DHH];
__device__ uint32_t g_mask[NN * (NN / 32)];

__device__ __forceinline__ float silu_f(float v) { return v / (1.0f + __expf(-v)); }

__device__ __forceinline__ float tf32r(float v) {
    uint32_t u;
    asm("cvt.rna.tf32.f32 %0, %1;" : "=r"(u) : "f"(v));
    return __uint_as_float(u);
}

__device__ __forceinline__ void mma8(float d[4], const uint32_t a[4], const uint32_t b[2]) {
    asm volatile("mma.sync.aligned.m16n8k8.row.col.f32.tf32.tf32.f32 "
                 "{%0,%1,%2,%3}, {%4,%5,%6,%7}, {%8,%9}, {%0,%1,%2,%3};\n"
                 : "+f"(d[0]), "+f"(d[1]), "+f"(d[2]), "+f"(d[3])
                 : "r"(a[0]), "r"(a[1]), "r"(a[2]), "r"(a[3]), "r"(b[0]), "r"(b[1]));
}

__device__ __forceinline__ void red2(float* p, float x, float y) {
    asm volatile("red.global.add.v2.f32 [%0], {%1,%2};" :: "l"(p), "f"(x), "f"(y) : "memory");
}

__device__ __forceinline__ void cpasync16(uint32_t smem_addr, const void* gptr) {
    asm volatile("cp.async.cg.shared.global [%0], [%1], 16;\n" :: "r"(smem_addr), "l"(gptr));
}
__device__ __forceinline__ void cp_commit() { asm volatile("cp.async.commit_group;\n" ::); }
__device__ __forceinline__ void cp_wait0() { asm volatile("cp.async.wait_group 0;\n" ::); }

__global__ void zero_agg_kernel() {
    int i = blockIdx.x * blockDim.x + threadIdx.x;
    ((float4*)g_agg)[i] = make_float4(0.f, 0.f, 0.f, 0.f);
}

// ============ prep: transpose + tf32-round ew2, ew1[257:273] ============
__global__ void prep_kernel(const float* __restrict__ ew1, const float* __restrict__ ew2) {
    int idx = blockIdx.x * blockDim.x + threadIdx.x;
    {
        int n = idx >> 8, k = idx & 255;
        g_ew2t[idx] = tf32r(ew2[k * HH + n]);
    }
    if (idx < HH * EDD) {
        int n = idx >> 4, k = idx & 15;
        g_ew1et[idx] = tf32r(ew1[(257 + k) * HH + n]);
    }
}

// ============ mask: exact-fp32 radius bitset ============
__global__ __launch_bounds__(256) void mask_kernel(const float* __restrict__ coords) {
    int w = (blockIdx.x * 256 + threadIdx.x) >> 5;   // row
    int lane = threadIdx.x & 31;
    float cx = coords[w * 3], cy = coords[w * 3 + 1], cz = coords[w * 3 + 2];
    for (int j0 = 0; j0 < NN; j0 += 32) {
        int j = j0 + lane;
        float dx = cx - coords[j * 3], dy = cy - coords[j * 3 + 1], dz = cz - coords[j * 3 + 2];
        float d2 = dx * dx + dy * dy + dz * dz;
        uint32_t bal = __ballot_sync(0xffffffffu, d2 <= 100.0f);
        if (lane == 0) g_mask[w * 256 + (j0 >> 5)] = bal;
    }
}

// ============ pre: P1/P2 = x @ ew1 halves ============
#define PRE_SMEM ((64 * 132 + 16 * 260) * 4)
__global__ __launch_bounds__(256, 1) void pre_kernel(
    const float* __restrict__ x, const float* __restrict__ ew1)
{
    extern __shared__ float sm[];
    float* sX = sm;
    float* sW = sm + 64 * 132;

    const int t = threadIdx.x, n0 = blockIdx.x * 64;
    const int part = blockIdx.y;
    const float* w = ew1 + part * 128 * HH;
    float* P = (part == 0) ? g_P1 : g_P2;
    const int ty = t >> 4, tx = t & 15, r0 = ty << 2, c0 = tx << 4;

    const float4* x4 = (const float4*)x;
    float4* sX4 = (float4*)sX;
    for (int idx = t; idx < 64 * 32; idx += 256) {
        int e = idx >> 5, f = idx & 31;
        sX4[e * 33 + f] = x4[(n0 + e) * 32 + f];
    }
    __syncthreads();

    float acc[4][16];
#pragma unroll
    for (int i = 0; i < 4; i++)
#pragma unroll
        for (int j = 0; j < 16; j++) acc[i][j] = 0.f;

    for (int k0 = 0; k0 < 128; k0 += 16) {
        float4* sWr = (float4*)(sW + ty * 260);
        const float4* w4 = (const float4*)(w + (k0 + ty) * HH);
#pragma unroll
        for (int j = 0; j < 4; j++) sWr[tx * 4 + j] = w4[tx * 4 + j];
        __syncthreads();
#pragma unroll
        for (int kk = 0; kk < 16; kk++) {
            float wv[16];
            const float4* wp = (const float4*)(sW + kk * 260 + c0);
            *((float4*)&wv[0]) = wp[0]; *((float4*)&wv[4]) = wp[1];
            *((float4*)&wv[8]) = wp[2]; *((float4*)&wv[12]) = wp[3];
            float a0 = sX[(r0 + 0) * 132 + k0 + kk], a1 = sX[(r0 + 1) * 132 + k0 + kk];
            float a2 = sX[(r0 + 2) * 132 + k0 + kk], a3 = sX[(r0 + 3) * 132 + k0 + kk];
#pragma unroll
            for (int j = 0; j < 16; j++) {
                acc[0][j] = fmaf(a0, wv[j], acc[0][j]);
                acc[1][j] = fmaf(a1, wv[j], acc[1][j]);
                acc[2][j] = fmaf(a2, wv[j], acc[2][j]);
                acc[3][j] = fmaf(a3, wv[j], acc[3][j]);
            }
        }
        __syncthreads();
    }
#pragma unroll
    for (int i = 0; i < 4; i++)
#pragma unroll
        for (int j = 0; j < 4; j++)
            ((float4*)P)[(n0 + r0 + i) * 64 + (c0 >> 2) + j] =
                make_float4(acc[i][4*j], acc[i][4*j+1], acc[i][4*j+2], acc[i][4*j+3]);
}

// ================= edge MLP (unchanged from R5) =================
#define SS 260
#define BES 24
#define B2S 24
#define ATS 20
#define OFF_SBE   (128 * SS)
#define OFF_SB2   (OFF_SBE + 256 * BES)
#define OFF_SAT   (OFF_SB2 + 2 * 256 * B2S)
#define OFF_RAD   (OFF_SAT + 128 * ATS)
#define OFF_META  (OFF_RAD + 128)
#define EDGE_SMEM ((OFF_META + 256) * 4)

__global__ __launch_bounds__(512, 1) void edge_kernel(
    const float* __restrict__ coords,
    const float* __restrict__ eattr, const int* __restrict__ eidx,
    const float* __restrict__ ew1, const float* __restrict__ eb1,
    const float* __restrict__ eb2)
{
    extern __shared__ float sm[];
    float* sS = sm;
    float* sBe = sm + OFF_SBE;
    float* sB2 = sm + OFF_SB2;
    float* sAttr = sm + OFF_SAT;
    float* sRad = sm + OFF_RAD;
    int* sRow = (int*)(sm + OFF_META);
    int* sCol = sRow + 128;

    const int t = threadIdx.x;
    const int lane = t & 31, wid = t >> 5;
    const int rg = wid & 3, cg = wid >> 2;
    const int e0 = blockIdx.x * 128;
    const uint32_t sb2_base = (uint32_t)__cvta_generic_to_shared(sB2);

#pragma unroll
    for (int rep = 0; rep < 2; rep++) {
        int idx = t + rep * 512;
        int nn = idx >> 2, qq = idx & 3;
        cpasync16(sb2_base + (nn * B2S + qq * 4) * 4, g_ew2t + nn * HH + qq * 4);
    }
    cp_commit();

    if (t < 128) {
        int e = e0 + t;
        int r = eidx[e], c = eidx[NE + e];
        sRow[t] = r; sCol[t] = c;
        float dx = coords[3*r+0]-coords[3*c+0];
        float dy = coords[3*r+1]-coords[3*c+1];
        float dz = coords[3*r+2]-coords[3*c+2];
        sRad[t] = dx*dx + dy*dy + dz*dz;
    }
    for (int idx = t; idx < 128 * 16; idx += 512) {
        int e = idx >> 4, j = idx & 15;
        sAttr[e * ATS + j] = tf32r(eattr[(e0 + e) * EDD + j]);
    }
    for (int idx = t; idx < 256 * 4; idx += 512) {
        int n = idx >> 2, q = idx & 3;
        *(float4*)(sBe + n * BES + q * 4) = *(const float4*)(g_ew1et + n * EDD + q * 4);
    }
    __syncthreads();

    {
        const float4* P1_4 = (const float4*)g_P1;
        const float4* P2_4 = (const float4*)g_P2;
        const float4* WR4 = (const float4*)(ew1 + 256 * HH);
        const float4* B14 = (const float4*)eb1;
        for (int idx = t; idx < 128 * 64; idx += 512) {
            int e = idx >> 6, f = idx & 63;
            float4 p1 = P1_4[sRow[e] * 64 + f];
            float4 p2 = P2_4[sCol[e] * 64 + f];
            float4 wr = WR4[f], bb = B14[f];
            float rad = sRad[e];
            float4 s;
            s.x = p1.x + p2.x + rad * wr.x + bb.x;
            s.y = p1.y + p2.y + rad * wr.y + bb.y;
            s.z = p1.z + p2.z + rad * wr.z + bb.z;
            s.w = p1.w + p2.w + rad * wr.w + bb.w;
            *(float4*)(sS + e * SS + f * 4) = s;
        }
    }
    __syncthreads();

    const int arow = rg * 32 + (lane >> 2);
    const int brow = cg * 64 + (lane >> 2);
    const int kl = lane & 3;
    const int g = lane >> 2;
    const int cb = cg * 64 + 2 * kl;

    float acc[2][8][4];
#pragma unroll
    for (int rf = 0; rf < 2; rf++) {
        int rbase = rg * 32 + rf * 16 + g;
#pragma unroll
        for (int nf = 0; nf < 8; nf++) {
            int c = cb + nf * 8;
            float2 v0 = *(const float2*)(sS + rbase * SS + c);
            float2 v1 = *(const float2*)(sS + (rbase + 8) * SS + c);
            acc[rf][nf][0] = v0.x; acc[rf][nf][1] = v0.y;
            acc[rf][nf][2] = v1.x; acc[rf][nf][3] = v1.y;
        }
    }

#pragma unroll
    for (int ks = 0; ks < 16; ks += 8) {
        const float* ap = sAttr + arow * ATS + ks + kl;
        uint32_t a0[4], a1[4];
        a0[0] = __float_as_uint(ap[0]);
        a0[1] = __float_as_uint(ap[8 * ATS]);
        a0[2] = __float_as_uint(ap[4]);
        a0[3] = __float_as_uint(ap[8 * ATS + 4]);
        a1[0] = __float_as_uint(ap[16 * ATS]);
        a1[1] = __float_as_uint(ap[24 * ATS]);
        a1[2] = __float_as_uint(ap[16 * ATS + 4]);
        a1[3] = __float_as_uint(ap[24 * ATS + 4]);
        const float* bp = sBe + brow * BES + ks + kl;
#pragma unroll
        for (int nf = 0; nf < 8; nf++) {
            uint32_t b[2];
            b[0] = __float_as_uint(bp[nf * 8 * BES]);
            b[1] = __float_as_uint(bp[nf * 8 * BES + 4]);
            mma8(acc[0][nf], a0, b);
            mma8(acc[1][nf], a1, b);
        }
    }

    float* sH = sS;
    {
        const int row0 = rg * 32 + g;
#pragma unroll
        for (int rf = 0; rf < 2; rf++) {
#pragma unroll
            for (int nf = 0; nf < 8; nf++) {
                int c = cb + nf * 8;
                float2 v0, v1;
                v0.x = tf32r(silu_f(acc[rf][nf][0]));
                v0.y = tf32r(silu_f(acc[rf][nf][1]));
                v1.x = tf32r(silu_f(acc[rf][nf][2]));
                v1.y = tf32r(silu_f(acc[rf][nf][3]));
                *(float2*)(sH + (row0 + rf * 16) * SS + c)     = v0;
                *(float2*)(sH + (row0 + rf * 16 + 8) * SS + c) = v1;
            }
        }
    }

#pragma unroll
    for (int rf = 0; rf < 2; rf++)
#pragma unroll
        for (int nf = 0; nf < 8; nf++)
#pragma unroll
            for (int j = 0; j < 4; j++) acc[rf][nf][j] = 0.f;

    for (int kb = 0; kb < 16; kb++) {
        cp_wait0();
        __syncthreads();
        if (kb + 1 < 16) {
            int koff = (kb + 1) * 16;
            uint32_t dstb = sb2_base + (((kb + 1) & 1) * 256 * B2S) * 4;
#pragma unroll
            for (int rep = 0; rep < 2; rep++) {
                int idx = t + rep * 512;
                int nn = idx >> 2, qq = idx & 3;
                cpasync16(dstb + (nn * B2S + qq * 4) * 4, g_ew2t + nn * HH + koff + qq * 4);
            }
            cp_commit();
        }
        const float* bufB = sB2 + (kb & 1) * 256 * B2S;
        int k0 = kb * 16;
#pragma unroll
        for (int ks = 0; ks < 16; ks += 8) {
            const float* ap = sH + arow * SS + k0 + ks + kl;
            uint32_t a0[4], a1[4];
            a0[0] = __float_as_uint(ap[0]);
            a0[1] = __float_as_uint(ap[8 * SS]);
            a0[2] = __float_as_uint(ap[4]);
            a0[3] = __float_as_uint(ap[8 * SS + 4]);
            a1[0] = __float_as_uint(ap[16 * SS]);
            a1[1] = __float_as_uint(ap[24 * SS]);
            a1[2] = __float_as_uint(ap[16 * SS + 4]);
            a1[3] = __float_as_uint(ap[24 * SS + 4]);
            const float* bp = bufB + brow * B2S + ks + kl;
#pragma unroll
            for (int nf = 0; nf < 8; nf++) {
                uint32_t b[2];
                b[0] = __float_as_uint(bp[nf * 8 * B2S]);
                b[1] = __float_as_uint(bp[nf * 8 * B2S + 4]);
                mma8(acc[0][nf], a0, b);
                mma8(acc[1][nf], a1, b);
            }
        }
    }

    {
        const int row0 = rg * 32 + g;
#pragma unroll
        for (int rf = 0; rf < 2; rf++) {
            int node0 = sRow[row0 + rf * 16];
            int node1 = sRow[row0 + rf * 16 + 8];
#pragma unroll
            for (int nf = 0; nf < 8; nf++) {
                int c = cb + nf * 8;
                float b0 = eb2[c], b1 = eb2[c + 1];
                red2(&g_agg[node0 * HH + c], silu_f(acc[rf][nf][0] + b0),
                                             silu_f(acc[rf][nf][1] + b1));
                red2(&g_agg[node1 * HH + c], silu_f(acc[rf][nf][2] + b0),
                                             silu_f(acc[rf][nf][3] + b1));
            }
        }
    }
}

// ================= node MLP + residual =================
#define NODE_SMEM ((64 * 388 + 16 * 260) * 4)
__global__ __launch_bounds__(256, 1) void node_kernel(
    const float* __restrict__ x,
    const float* __restrict__ nw1, const float* __restrict__ nb1,
    const float* __restrict__ nw2, const float* __restrict__ nb2)
{
    extern __shared__ float sm[];
    float* sM = sm;
    float* sW = sm + 64 * 388;

    const int t = threadIdx.x, n0 = blockIdx.x * 64;
    const int ty = t >> 4, tx = t & 15, r0 = ty << 2;

    const float4* x4 = (const float4*)x;
    const float4* agg4 = (const float4*)g_agg;
    float4* sM4 = (float4*)sM;
    for (int idx = t; idx < 64*32; idx += 256) {
        int e = idx >> 5, f = idx & 31;
        sM4[e*97 + f] = x4[(n0+e)*32 + f];
    }
    for (int idx = t; idx < 64*64; idx += 256) {
        int e = idx >> 6, f = idx & 63;
        sM4[e*97 + 32 + f] = agg4[(n0+e)*64 + f];
    }
    __syncthreads();

    const int c0 = tx << 4;
    float acc[4][16];
#pragma unroll
    for (int i = 0; i < 4; i++)
#pragma unroll
        for (int j = 0; j < 16; j++) acc[i][j] = 0.f;

    for (int k0 = 0; k0 < 384; k0 += 16) {
        float4* sWr = (float4*)(sW + ty*260);
        const float4* w4 = (const float4*)(nw1 + (k0+ty)*HH);
#pragma unroll
        for (int j = 0; j < 4; j++) sWr[tx*4+j] = w4[tx*4+j];
        __syncthreads();
#pragma unroll
        for (int kk = 0; kk < 16; kk++) {
            float w[16];
            const float4* wp = (const float4*)(sW + kk*260 + c0);
            *((float4*)&w[0]) = wp[0]; *((float4*)&w[4]) = wp[1];
            *((float4*)&w[8]) = wp[2]; *((float4*)&w[12]) = wp[3];
            float a0 = sM[(r0+0)*388 + k0+kk], a1 = sM[(r0+1)*388 + k0+kk];
            float a2 = sM[(r0+2)*388 + k0+kk], a3 = sM[(r0+3)*388 + k0+kk];
#pragma unroll
            for (int j = 0; j < 16; j++) {
                acc[0][j] = fmaf(a0, w[j], acc[0][j]);
                acc[1][j] = fmaf(a1, w[j], acc[1][j]);
                acc[2][j] = fmaf(a2, w[j], acc[2][j]);
                acc[3][j] = fmaf(a3, w[j], acc[3][j]);
            }
        }
        __syncthreads();
    }

    float* sH = sm;
#pragma unroll
    for (int i = 0; i < 4; i++)
#pragma unroll
        for (int j = 0; j < 16; j++)
            sH[(r0+i)*260 + c0+j] = silu_f(acc[i][j] + nb1[c0+j]);
    __syncthreads();

    const int c1 = tx << 3;
    float acc2[4][8];
#pragma unroll
    for (int i = 0; i < 4; i++)
#pragma unroll
        for (int j = 0; j < 8; j++) acc2[i][j] = 0.f;

    for (int k0 = 0; k0 < 256; k0 += 16) {
        float4* sWr = (float4*)(sW + ty*132);
        const float4* w4 = (const float4*)(nw2 + (k0+ty)*DD);
        sWr[tx*2+0] = w4[tx*2+0];
        sWr[tx*2+1] = w4[tx*2+1];
        __syncthreads();
#pragma unroll
        for (int kk = 0; kk < 16; kk++) {
            float w[8];
            const float4* wp = (const float4*)(sW + kk*132 + c1);
            *((float4*)&w[0]) = wp[0]; *((float4*)&w[4]) = wp[1];
            float a0 = sH[(r0+0)*260 + k0+kk], a1 = sH[(r0+1)*260 + k0+kk];
            float a2 = sH[(r0+2)*260 + k0+kk], a3 = sH[(r0+3)*260 + k0+kk];
#pragma unroll
            for (int j = 0; j < 8; j++) {
                acc2[0][j] = fmaf(a0, w[j], acc2[0][j]);
                acc2[1][j] = fmaf(a1, w[j], acc2[1][j]);
                acc2[2][j] = fmaf(a2, w[j], acc2[2][j]);
                acc2[3][j] = fmaf(a3, w[j], acc2[3][j]);
            }
        }
        __syncthreads();
    }

#pragma unroll
    for (int i = 0; i < 4; i++) {
        int node = n0 + r0 + i;
        float4 xa = x4[node*32 + (c1>>2)];
        float4 xb = x4[node*32 + (c1>>2) + 1];
        float4 o0, o1;
        o0.x = acc2[i][0]+nb2[c1+0]+xa.x; o0.y = acc2[i][1]+nb2[c1+1]+xa.y;
        o0.z = acc2[i][2]+nb2[c1+2]+xa.z; o0.w = acc2[i][3]+nb2[c1+3]+xa.w;
        o1.x = acc2[i][4]+nb2[c1+4]+xb.x; o1.y = acc2[i][5]+nb2[c1+5]+xb.y;
        o1.z = acc2[i][6]+nb2[c1+6]+xb.z; o1.w = acc2[i][7]+nb2[c1+7]+xb.w;
        ((float4*)g_xgnn)[node*32 + (c1>>2)]     = o0;
        ((float4*)g_xgnn)[node*32 + (c1>>2) + 1] = o1;
    }
}

// ================= QKV projection (k rounded, v transposed+rounded) =================
#define QKV_SMEM ((64 * 132 + 128 * 68) * 4)
__global__ __launch_bounds__(256, 2) void qkv_kernel(
    const float* __restrict__ x, const float* __restrict__ wq,
    const float* __restrict__ wk, const float* __restrict__ wv)
{
    extern __shared__ float sm[];
    float* sX = sm;
    float* sW = sm + 64 * 132;

    const int t = threadIdx.x, n0 = blockIdx.x * 64;
    const float* w = (blockIdx.y == 0) ? wq : (blockIdx.y == 1) ? wk : wv;

    const float4* x4 = (const float4*)x;
    float4* sX4 = (float4*)sX;
    for (int idx = t; idx < 64*32; idx += 256) {
        int e = idx >> 5, f = idx & 31;
        sX4[e*33 + f] = x4[(n0+e)*32 + f];
    }
    const float4* w4 = (const float4*)w;
    float4* sW4 = (float4*)sW;
    for (int idx = t; idx < 128*16; idx += 256) {
        int r = idx >> 4, f = idx & 15;
        sW4[r*17 + f] = w4[r*16 + f];
    }
    __syncthreads();

    const int ty = t >> 4, tx = t & 15, r0 = ty << 2;
    float acc[4][4];
#pragma unroll
    for (int i = 0; i < 4; i++)
#pragma unroll
        for (int j = 0; j < 4; j++) acc[i][j] = 0.f;

    for (int k = 0; k < 128; k++) {
        float4 wv4 = sW4[k*17 + tx];
#pragma unroll
        for (int i = 0; i < 4; i++) {
            float a = sX[(r0+i)*132 + k];
            acc[i][0] = fmaf(a, wv4.x, acc[i][0]);
            acc[i][1] = fmaf(a, wv4.y, acc[i][1]);
            acc[i][2] = fmaf(a, wv4.z, acc[i][2]);
            acc[i][3] = fmaf(a, wv4.w, acc[i][3]);
        }
    }
    if (blockIdx.y == 0) {
#pragma unroll
        for (int i = 0; i < 4; i++)
            ((float4*)g_q)[(n0+r0+i)*16 + tx] =
                make_float4(acc[i][0], acc[i][1], acc[i][2], acc[i][3]);
    } else if (blockIdx.y == 1) {
#pragma unroll
        for (int i = 0; i < 4; i++)
            ((float4*)g_k)[(n0+r0+i)*16 + tx] =
                make_float4(tf32r(acc[i][0]), tf32r(acc[i][1]), tf32r(acc[i][2]), tf32r(acc[i][3]));
    } else {
#pragma unroll
        for (int i = 0; i < 4; i++)
#pragma unroll
            for (int j = 0; j < 4; j++)
                g_vt[(tx*4 + j) * NN + n0 + r0 + i] = tf32r(acc[i][j]);
    }
}

// ================= MMA flash attention (split-j x4, mask bitset) =================
#define SKS 68
#define SPS 68
#define ATTN_SMEM ((64*SKS + 64*SKS + 4*16*SPS) * 4)
__global__ __launch_bounds__(128) void attn_kernel()
{
    extern __shared__ float sm[];
    float* sK  = sm;
    float* sVt = sm + 64 * SKS;
    float* sP  = sm + 128 * SKS;

    const int t = threadIdx.x;
    const int lane = t & 31, wid = t >> 5;
    const int split = blockIdx.y;
    const int qrow0 = blockIdx.x * 64 + wid * 16;
    const int arow = lane >> 2;          // 0..7
    const int kl = lane & 3;

    // Q fragments (scaled + rounded), resident in registers
    uint32_t qf[8][4];
#pragma unroll
    for (int ks = 0; ks < 8; ks++) {
        const float* qp = g_q + qrow0 * DHH + ks * 8 + kl;
        qf[ks][0] = __float_as_uint(tf32r(qp[arow * DHH] * 0.125f));
        qf[ks][1] = __float_as_uint(tf32r(qp[(arow + 8) * DHH] * 0.125f));
        qf[ks][2] = __float_as_uint(tf32r(qp[arow * DHH + 4] * 0.125f));
        qf[ks][3] = __float_as_uint(tf32r(qp[(arow + 8) * DHH + 4] * 0.125f));
    }

    float m0 = -1e30f, m1 = -1e30f, l0 = 0.f, l1 = 0.f;
    float accO[8][4];
#pragma unroll
    for (int nf = 0; nf < 8; nf++)
#pragma unroll
        for (int j = 0; j < 4; j++) accO[nf][j] = 0.f;

    float* myP = sP + wid * 16 * SPS;
    const int row0 = qrow0 + arow, row1 = row0 + 8;

    for (int jt = 0; jt < NN / 4 / 64; jt++) {
        const int j0 = split * (NN / 4) + jt * 64;
        __syncthreads();
        for (int idx = t; idx < 64 * 16; idx += 128) {
            int r = idx >> 4, f = idx & 15;
            ((float4*)(sK + r * SKS))[f]  = ((const float4*)g_k)[(j0 + r) * 16 + f];
            ((float4*)(sVt + r * SKS))[f] = ((const float4*)g_vt)[r * (NN / 4) + (j0 >> 2) + f];
        }
        __syncthreads();

        // S = Q @ K^T
        float s[8][4];
#pragma unroll
        for (int nf = 0; nf < 8; nf++)
#pragma unroll
            for (int j = 0; j < 4; j++) s[nf][j] = 0.f;
#pragma unroll
        for (int ks = 0; ks < 8; ks++) {
            const float* bp = sK + arow * SKS + ks * 8 + kl;
#pragma unroll
            for (int nf = 0; nf < 8; nf++) {
                uint32_t b[2];
                b[0] = __float_as_uint(bp[nf * 8 * SKS]);
                b[1] = __float_as_uint(bp[nf * 8 * SKS + 4]);
                mma8(s[nf], qf[ks], b);
            }
        }

        // mask + row max
        uint32_t mw00 = g_mask[row0 * 256 + (j0 >> 5)];
        uint32_t mw01 = g_mask[row0 * 256 + (j0 >> 5) + 1];
        uint32_t mw10 = g_mask[row1 * 256 + (j0 >> 5)];
        uint32_t mw11 = g_mask[row1 * 256 + (j0 >> 5) + 1];
        float tmax0 = -1e30f, tmax1 = -1e30f;
#pragma unroll
        for (int nf = 0; nf < 8; nf++) {
            int c0 = nf * 8 + 2 * kl, c1 = c0 + 1;
            uint32_t w0r0 = (c0 < 32) ? mw00 : mw01;
            uint32_t w1r0 = (c1 < 32) ? mw00 : mw01;
            uint32_t w0r1 = (c0 < 32) ? mw10 : mw11;
            uint32_t w1r1 = (c1 < 32) ? mw10 : mw11;
            s[nf][0] = ((w0r0 >> (c0 & 31)) & 1) ? s[nf][0] : -1e30f;
            s[nf][1] = ((w1r0 >> (c1 & 31)) & 1) ? s[nf][1] : -1e30f;
            s[nf][2] = ((w0r1 >> (c0 & 31)) & 1) ? s[nf][2] : -1e30f;
            s[nf][3] = ((w1r1 >> (c1 & 31)) & 1) ? s[nf][3] : -1e30f;
            tmax0 = fmaxf(tmax0, fmaxf(s[nf][0], s[nf][1]));
            tmax1 = fmaxf(tmax1, fmaxf(s[nf][2], s[nf][3]));
        }
        tmax0 = fmaxf(tmax0, __shfl_xor_sync(0xffffffffu, tmax0, 1));
        tmax0 = fmaxf(tmax0, __shfl_xor_sync(0xffffffffu, tmax0, 2));
        tmax1 = fmaxf(tmax1, __shfl_xor_sync(0xffffffffu, tmax1, 1));
        tmax1 = fmaxf(tmax1, __shfl_xor_sync(0xffffffffu, tmax1, 2));

        float mn0 = fmaxf(m0, tmax0), mn1 = fmaxf(m1, tmax1);
        float cr0 = __expf(m0 - mn0), cr1 = __expf(m1 - mn1);
        float g0 = (mn0 > -1e29f) ? 1.f : 0.f;
        float g1 = (mn1 > -1e29f) ? 1.f : 0.f;
        l0 *= cr0; l1 *= cr1;
        m0 = mn0; m1 = mn1;
#pragma unroll
        for (int nf = 0; nf < 8; nf++) {
            accO[nf][0] *= cr0; accO[nf][1] *= cr0;
            accO[nf][2] *= cr1; accO[nf][3] *= cr1;
        }

        float sum0 = 0.f, sum1 = 0.f;
#pragma unroll
        for (int nf = 0; nf < 8; nf++) {
            int c0 = nf * 8 + 2 * kl;
            float p00 = g0 * __expf(s[nf][0] - mn0);
            float p01 = g0 * __expf(s[nf][1] - mn0);
            float p10 = g1 * __expf(s[nf][2] - mn1);
            float p11 = g1 * __expf(s[nf][3] - mn1);
            sum0 += p00 + p01;
            sum1 += p10 + p11;
            *(float2*)(myP + arow * SPS + c0)       = make_float2(tf32r(p00), tf32r(p01));
            *(float2*)(myP + (arow + 8) * SPS + c0) = make_float2(tf32r(p10), tf32r(p11));
        }
        sum0 += __shfl_xor_sync(0xffffffffu, sum0, 1);
        sum0 += __shfl_xor_sync(0xffffffffu, sum0, 2);
        sum1 += __shfl_xor_sync(0xffffffffu, sum1, 1);
        sum1 += __shfl_xor_sync(0xffffffffu, sum1, 2);
        l0 += sum0; l1 += sum1;
        __syncwarp();

        // O += P @ V  (B = V^T tile)
#pragma unroll
        for (int ks = 0; ks < 8; ks++) {
            const float* ap = myP + arow * SPS + ks * 8 + kl;
            uint32_t a[4];
            a[0] = __float_as_uint(ap[0]);
            a[1] = __float_as_uint(ap[8 * SPS]);
            a[2] = __float_as_uint(ap[4]);
            a[3] = __float_as_uint(ap[8 * SPS + 4]);
            const float* bp = sVt + arow * SKS + ks * 8 + kl;
#pragma unroll
            for (int nf = 0; nf < 8; nf++) {
                uint32_t b[2];
                b[0] = __float_as_uint(bp[nf * 8 * SKS]);
                b[1] = __float_as_uint(bp[nf * 8 * SKS + 4]);
                mma8(accO[nf], a, b);
            }
        }
        __syncwarp();
    }

    // write partials
#pragma unroll
    for (int nf = 0; nf < 8; nf++) {
        int c = nf * 8 + 2 * kl;
        *(float2*)(g_po + (split * NN + row0) * DHH + c) = make_float2(accO[nf][0], accO[nf][1]);
        *(float2*)(g_po + (split * NN + row1) * DHH + c) = make_float2(accO[nf][2], accO[nf][3]);
    }
    if (kl == 0) {
        g_pm[split * NN + row0] = m0; g_pl[split * NN + row0] = l0;
        g_pm[split * NN + row1] = m1; g_pl[split * NN + row1] = l1;
    }
}

__global__ __launch_bounds__(256) void attn_combine_kernel()
{
    int tg = blockIdx.x * 256 + threadIdx.x;
    int row = tg >> 2, grp = (tg & 3) * 4;
    float m0 = g_pm[row], m1 = g_pm[NN + row], m2 = g_pm[2*NN + row], m3 = g_pm[3*NN + row];
    float M = fmaxf(fmaxf(m0, m1), fmaxf(m2, m3));
    float w0 = __expf(m0 - M), w1 = __expf(m1 - M), w2 = __expf(m2 - M), w3 = __expf(m3 - M);
    float L = w0 * g_pl[row] + w1 * g_pl[NN + row] + w2 * g_pl[2*NN + row] + w3 * g_pl[3*NN + row];
    float inv = 1.0f / L;
    const float4* po = (const float4*)g_po;
#pragma unroll
    for (int qq = 0; qq < 4; qq++) {
        float4 a = po[(0*NN + row) * 16 + grp + qq];
        float4 b = po[(1*NN + row) * 16 + grp + qq];
        float4 c = po[(2*NN + row) * 16 + grp + qq];
        float4 d = po[(3*NN + row) * 16 + grp + qq];
        float4 r;
        r.x = (w0*a.x + w1*b.x + w2*c.x + w3*d.x) * inv;
        r.y = (w0*a.y + w1*b.y + w2*c.y + w3*d.y) * inv;
        r.z = (w0*a.z + w1*b.z + w2*c.z + w3*d.z) * inv;
        r.w = (w0*a.w + w1*b.w + w2*c.w + w3*d.w) * inv;
        ((float4*)g_oh)[row * 16 + grp + qq] = r;
    }
}

// ================= combiner =================
#define CMB_SMEM (29248 * 4)
__global__ __launch_bounds__(256, 1) void comb_kernel(
    const float* __restrict__ wo,
    const float* __restrict__ cmw1, const float* __restrict__ cmb1,
    const float* __restrict__ ln_g, const float* __restrict__ ln_b,
    const float* __restrict__ cmw2, const float* __restrict__ cmb2,
    float* __restrict__ out)
{
    extern __shared__ float sm[];
    float* sC = sm;
    float* sH = sm + 8448;
    float* sW = sm + 25088;
    float* sOH = sm + 8448;
    float* sWo = sm + 12800;

    const int t = threadIdx.x, n0 = blockIdx.x * 64;
    const int ty = t >> 4, tx = t & 15, r0 = ty << 2;

    for (int idx = t; idx < 64*16; idx += 256) {
        int e = idx >> 4, f = idx & 15;
        ((float4*)sOH)[e*17 + f] = ((const float4*)g_oh)[(n0+e)*16 + f];
    }
    for (int idx = t; idx < 64*32; idx += 256) {
        int r = idx >> 5, f = idx & 31;
        ((float4*)sWo)[r*33 + f] = ((const float4*)wo)[r*32 + f];
    }
    __syncthreads();

    {
        const int c1 = tx << 3;
        float acc[4][8];
#pragma unroll
        for (int i = 0; i < 4; i++)
#pragma unroll
            for (int j = 0; j < 8; j++) acc[i][j] = 0.f;
        for (int k = 0; k < 64; k++) {
            float4 w0 = ((float4*)sWo)[k*33 + (c1>>2)];
            float4 w1 = ((float4*)sWo)[k*33 + (c1>>2) + 1];
#pragma unroll
            for (int i = 0; i < 4; i++) {
                float a = sOH[(r0+i)*68 + k];
                acc[i][0]=fmaf(a,w0.x,acc[i][0]); acc[i][1]=fmaf(a,w0.y,acc[i][1]);
                acc[i][2]=fmaf(a,w0.z,acc[i][2]); acc[i][3]=fmaf(a,w0.w,acc[i][3]);
                acc[i][4]=fmaf(a,w1.x,acc[i][4]); acc[i][5]=fmaf(a,w1.y,acc[i][5]);
                acc[i][6]=fmaf(a,w1.z,acc[i][6]); acc[i][7]=fmaf(a,w1.w,acc[i][7]);
            }
        }
        __syncthreads();
#pragma unroll
        for (int i = 0; i < 4; i++)
#pragma unroll
            for (int j = 0; j < 8; j++)
                sC[(r0+i)*132 + c1+j] = acc[i][j] + g_xgnn[(n0+r0+i)*128 + c1+j];
    }
    __syncthreads();

    {
        const int c0 = tx << 4;
        float acc[4][16];
#pragma unroll
        for (int i = 0; i < 4; i++)
#pragma unroll
            for (int j = 0; j < 16; j++) acc[i][j] = 0.f;
        for (int k0 = 0; k0 < 128; k0 += 16) {
            float4* sWr = (float4*)(sW + ty*260);
            const float4* w4 = (const float4*)(cmw1 + (k0+ty)*HH);
#pragma unroll
            for (int j = 0; j < 4; j++) sWr[tx*4+j] = w4[tx*4+j];
            __syncthreads();
#pragma unroll
            for (int kk = 0; kk < 16; kk++) {
                float w[16];
                const float4* wp = (const float4*)(sW + kk*260 + c0);
                *((float4*)&w[0]) = wp[0]; *((float4*)&w[4]) = wp[1];
                *((float4*)&w[8]) = wp[2]; *((float4*)&w[12]) = wp[3];
                float a0 = sC[(r0+0)*132 + k0+kk], a1 = sC[(r0+1)*132 + k0+kk];
                float a2 = sC[(r0+2)*132 + k0+kk], a3 = sC[(r0+3)*132 + k0+kk];
#pragma unroll
                for (int j = 0; j < 16; j++) {
                    acc[0][j] = fmaf(a0, w[j], acc[0][j]);
                    acc[1][j] = fmaf(a1, w[j], acc[1][j]);
                    acc[2][j] = fmaf(a2, w[j], acc[2][j]);
                    acc[3][j] = fmaf(a3, w[j], acc[3][j]);
                }
            }
            __syncthreads();
        }
#pragma unroll
        for (int i = 0; i < 4; i++)
#pragma unroll
            for (int j = 0; j < 16; j++)
                sH[(r0+i)*260 + c0+j] = fmaxf(acc[i][j] + cmb1[c0+j], 0.f);
    }
    __syncthreads();

    {
        int node = t >> 2, part = t & 3;
        float s = 0.f, sq = 0.f;
        const float* hrow = sH + node*260 + part*64;
#pragma unroll 16
        for (int i = 0; i < 64; i++) { float v = hrow[i]; s += v; sq += v*v; }
        s  += __shfl_xor_sync(0xffffffffu, s, 1);
        s  += __shfl_xor_sync(0xffffffffu, s, 2);
        sq += __shfl_xor_sync(0xffffffffu, sq, 1);
        sq += __shfl_xor_sync(0xffffffffu, sq, 2);
        float mu = s * (1.f/256.f);
        float var = sq * (1.f/256.f) - mu*mu;
        float rstd = rsqrtf(var + 1e-5f);
        float* hw = sH + node*260 + part*64;
#pragma unroll 16
        for (int i = 0; i < 64; i++) {
            int c = part*64 + i;
            hw[i] = (hw[i] - mu) * rstd * ln_g[c] + ln_b[c];
        }
    }
    __syncthreads();

    {
        const int c2 = tx << 2;
        float acc[4][4];
#pragma unroll
        for (int i = 0; i < 4; i++)
#pragma unroll
            for (int j = 0; j < 4; j++) acc[i][j] = 0.f;
        for (int k0 = 0; k0 < 256; k0 += 16) {
            float4* sWr = (float4*)(sW + ty*68);
            const float4* w4 = (const float4*)(cmw2 + (k0+ty)*YY);
            sWr[tx] = w4[tx];
            __syncthreads();
#pragma unroll
            for (int kk = 0; kk < 16; kk++) {
                float4 w = ((float4*)(sW + kk*68))[tx];
#pragma unroll
                for (int i = 0; i < 4; i++) {
                    float a = sH[(r0+i)*260 + k0+kk];
                    acc[i][0] = fmaf(a, w.x, acc[i][0]);
                    acc[i][1] = fmaf(a, w.y, acc[i][1]);
                    acc[i][2] = fmaf(a, w.z, acc[i][2]);
                    acc[i][3] = fmaf(a, w.w, acc[i][3]);
                }
            }
            __syncthreads();
        }
        float4 b = *(const float4*)(cmb2 + c2);
#pragma unroll
        for (int i = 0; i < 4; i++)
            ((float4*)out)[(n0+r0+i)*16 + tx] =
                make_float4(acc[i][0]+b.x, acc[i][1]+b.y, acc[i][2]+b.z, acc[i][3]+b.w);
    }
}

extern "C" void kernel_launch(void* const* d_in, const int* in_sizes, int n_in,
                              void* d_out, int out_size) {
    const float* x      = (const float*)d_in[0];
    const float* coords = (const float*)d_in[1];
    const float* eattr  = (const float*)d_in[2];
    const int*   eidx   = (const int*)  d_in[3];
    const float* ew1 = (const float*)d_in[4],  *eb1 = (const float*)d_in[5];
    const float* ew2 = (const float*)d_in[6],  *eb2 = (const float*)d_in[7];
    const float* nw1 = (const float*)d_in[8],  *nb1 = (const float*)d_in[9];
    const float* nw2 = (const float*)d_in[10], *nb2 = (const float*)d_in[11];
    const float* wq  = (const float*)d_in[12], *wk  = (const float*)d_in[13];
    const float* wv  = (const float*)d_in[14], *wo  = (const float*)d_in[15];
    const float* cmw1 = (const float*)d_in[16], *cmb1 = (const float*)d_in[17];
    const float* ln_g = (const float*)d_in[18], *ln_b = (const float*)d_in[19];
    const float* cmw2 = (const float*)d_in[20], *cmb2 = (const float*)d_in[21];
    float* out = (float*)d_out;

    cudaFuncSetAttribute(pre_kernel,  cudaFuncAttributeMaxDynamicSharedMemorySize, PRE_SMEM);
    cudaFuncSetAttribute(edge_kernel, cudaFuncAttributeMaxDynamicSharedMemorySize, EDGE_SMEM);
    cudaFuncSetAttribute(node_kernel, cudaFuncAttributeMaxDynamicSharedMemorySize, NODE_SMEM);
    cudaFuncSetAttribute(qkv_kernel,  cudaFuncAttributeMaxDynamicSharedMemorySize, QKV_SMEM);
    cudaFuncSetAttribute(attn_kernel, cudaFuncAttributeMaxDynamicSharedMemorySize, ATTN_SMEM);
    cudaFuncSetAttribute(comb_kernel, cudaFuncAttributeMaxDynamicSharedMemorySize, CMB_SMEM);

    prep_kernel<<<256, 256>>>(ew1, ew2);
    pre_kernel<<<dim3(NN / 64, 2), 256, PRE_SMEM>>>(x, ew1);
    zero_agg_kernel<<<NN * HH / 4 / 256, 256>>>();
    mask_kernel<<<NN / 8, 256>>>(coords);
    edge_kernel<<<NE / 128, 512, EDGE_SMEM>>>(coords, eattr, eidx, ew1, eb1, eb2);
    node_kernel<<<NN / 64, 256, NODE_SMEM>>>(x, nw1, nb1, nw2, nb2);
    qkv_kernel<<<dim3(NN / 64, 3), 256, QKV_SMEM>>>(x, wq, wk, wv);
    attn_kernel<<<dim3(NN / 64, 4), 128, ATTN_SMEM>>>();
    attn_combine_kernel<<<NN * 4 / 256, 256>>>();
    comb_kernel<<<NN / 64, 256, CMB_SMEM>>>(wo, cmw1, cmb1, ln_g, ln_b, cmw2, cmb2, out);
}